// round 3
// baseline (speedup 1.0000x reference)
#include <cuda_runtime.h>
#include <cuda_bf16.h>
#include <cstdint>

// ---------------------------------------------------------------------------
// MeshGraphEdgeMLPSum: out = LN( silu(efeat@We^T + Psrc[src] + Pdst[dst]) @ W2^T + b2 )
// Psrc = nfeat@Wsrc^T, Pdst = nfeat@Wdst^T + b1
// All GEMMs done as 2-way bf16-split (3-term) tensor-core MMA, fp32 accumulate.
// ---------------------------------------------------------------------------

#define LDW 136   // padded bf16 row stride (conflict-free fragment loads)
#define LDO 132   // padded fp32 row stride for LayerNorm staging

#define W_BYTES    (128 * LDW * 2)                 // 34816 B per bf16 matrix copy
#define SM_W0      0
#define SM_ACT     (4 * W_BYTES)                   // 139264
#define SM_ACT_LO  (SM_ACT + W_BYTES)              // 174080
#define SM_IDX_S   (SM_ACT + 2 * W_BYTES)          // 208896
#define SM_IDX_D   (SM_IDX_S + 512)                // 209408
#define SM_B2      (SM_IDX_D + 512)                // 209920
#define SM_G       (SM_B2 + 512)                   // 210432
#define SM_BETA    (SM_G + 512)                    // 210944
#define EDGE_SMEM  (SM_BETA + 512)                 // 211456
#define NODE_SMEM  (SM_IDX_S + 512)                // 209408 (weights + act + b1)

// Scratch (static device globals: the sanctioned no-alloc workaround)
__device__ __nv_bfloat16 g_Wedge[4][128 * LDW];    // We_hi, We_lo, W2_hi, W2_lo
__device__ __nv_bfloat16 g_Wnode[4][128 * LDW];    // Ws_hi, Ws_lo, Wd_hi, Wd_lo
__device__ float         g_P[50048 * 256];         // [node][0:128]=src proj, [128:256]=dst proj + b1

__device__ __forceinline__ void bsplit(float x, __nv_bfloat16& h, __nv_bfloat16& l) {
    h = __float2bfloat16(x);
    l = __float2bfloat16(x - __bfloat162float(h));
}

__device__ __forceinline__ uint32_t lds32(const void* p) {
    return *reinterpret_cast<const uint32_t*>(p);
}

__device__ __forceinline__ void mma16816(float* c, const uint32_t* a, uint32_t b0, uint32_t b1) {
    asm volatile(
        "mma.sync.aligned.m16n8k16.row.col.f32.bf16.bf16.f32 "
        "{%0,%1,%2,%3}, {%4,%5,%6,%7}, {%8,%9}, {%0,%1,%2,%3};\n"
        : "+f"(c[0]), "+f"(c[1]), "+f"(c[2]), "+f"(c[3])
        : "r"(a[0]), "r"(a[1]), "r"(a[2]), "r"(a[3]), "r"(b0), "r"(b1));
}

// C[128x128] += A[128x128] * W^T, A/W given as bf16 hi/lo splits in smem.
// Warp grid 4(M)x2(N): warp tile 32x64. acc[2][8][4].
__device__ __forceinline__ void gemm_tile(
    const __nv_bfloat16* Ah, const __nv_bfloat16* Al,
    const __nv_bfloat16* Wh, const __nv_bfloat16* Wl,
    float acc[2][8][4], int mbase, int nbase, int g, int t)
{
    #pragma unroll
    for (int k0 = 0; k0 < 128; k0 += 16) {
        uint32_t ah[2][4], al[2][4];
        #pragma unroll
        for (int mi = 0; mi < 2; mi++) {
            const __nv_bfloat16* p0 = Ah + (mbase + mi * 16 + g) * LDW + k0 + t * 2;
            const __nv_bfloat16* p1 = p0 + 8 * LDW;
            ah[mi][0] = lds32(p0);     ah[mi][1] = lds32(p1);
            ah[mi][2] = lds32(p0 + 8); ah[mi][3] = lds32(p1 + 8);
            const __nv_bfloat16* q0 = Al + (mbase + mi * 16 + g) * LDW + k0 + t * 2;
            const __nv_bfloat16* q1 = q0 + 8 * LDW;
            al[mi][0] = lds32(q0);     al[mi][1] = lds32(q1);
            al[mi][2] = lds32(q0 + 8); al[mi][3] = lds32(q1 + 8);
        }
        uint32_t bh[8][2], bl[8][2];
        #pragma unroll
        for (int ni = 0; ni < 8; ni++) {
            const __nv_bfloat16* p = Wh + (nbase + ni * 8 + g) * LDW + k0 + t * 2;
            bh[ni][0] = lds32(p); bh[ni][1] = lds32(p + 8);
            const __nv_bfloat16* q = Wl + (nbase + ni * 8 + g) * LDW + k0 + t * 2;
            bl[ni][0] = lds32(q); bl[ni][1] = lds32(q + 8);
        }
        // three split terms, spread so same-accumulator reuse distance is 16 MMAs
        #pragma unroll
        for (int ni = 0; ni < 8; ni++)
            #pragma unroll
            for (int mi = 0; mi < 2; mi++)
                mma16816(acc[mi][ni], ah[mi], bh[ni][0], bh[ni][1]);
        #pragma unroll
        for (int ni = 0; ni < 8; ni++)
            #pragma unroll
            for (int mi = 0; mi < 2; mi++)
                mma16816(acc[mi][ni], ah[mi], bl[ni][0], bl[ni][1]);
        #pragma unroll
        for (int ni = 0; ni < 8; ni++)
            #pragma unroll
            for (int mi = 0; mi < 2; mi++)
                mma16816(acc[mi][ni], al[mi], bh[ni][0], bh[ni][1]);
    }
}

__device__ __forceinline__ void zero_acc(float acc[2][8][4]) {
    #pragma unroll
    for (int mi = 0; mi < 2; mi++)
        #pragma unroll
        for (int ni = 0; ni < 8; ni++)
            #pragma unroll
            for (int j = 0; j < 4; j++)
                acc[mi][ni][j] = 0.f;
}

// ---------------------------------------------------------------------------
// Kernel 0: split all four weight matrices into padded bf16 hi/lo scratch.
// ---------------------------------------------------------------------------
__global__ void prep_weights(const float* we, const float* w2,
                             const float* ws, const float* wd)
{
    const float* src;
    __nv_bfloat16 *dh, *dl;
    switch (blockIdx.x) {
        case 0:  src = we; dh = g_Wedge[0]; dl = g_Wedge[1]; break;
        case 1:  src = w2; dh = g_Wedge[2]; dl = g_Wedge[3]; break;
        case 2:  src = ws; dh = g_Wnode[0]; dl = g_Wnode[1]; break;
        default: src = wd; dh = g_Wnode[2]; dl = g_Wnode[3]; break;
    }
    for (int i = threadIdx.x; i < 128 * 128; i += blockDim.x) {
        int r = i >> 7, c = i & 127;
        __nv_bfloat16 h, l;
        bsplit(src[i], h, l);
        dh[r * LDW + c] = h;
        dl[r * LDW + c] = l;
    }
}

// ---------------------------------------------------------------------------
// Kernel 1: node projections P[n, 0:128] = nfeat@Wsrc^T ; P[n,128:256] = nfeat@Wdst^T + b1
// ---------------------------------------------------------------------------
__global__ __launch_bounds__(256, 1)
void node_proj_kernel(const float* __restrict__ nfeat, const float* __restrict__ b1, int Nnodes)
{
    extern __shared__ char sm[];
    __nv_bfloat16* Wsm = (__nv_bfloat16*)(sm + SM_W0);
    __nv_bfloat16* Ah  = (__nv_bfloat16*)(sm + SM_ACT);
    __nv_bfloat16* Al  = (__nv_bfloat16*)(sm + SM_ACT_LO);
    float* s_b1 = (float*)(sm + SM_IDX_S);
    const int tid = threadIdx.x;

    {   // weights -> smem
        const uint32_t* s = (const uint32_t*)g_Wnode;
        uint32_t* d = (uint32_t*)Wsm;
        for (int i = tid; i < 4 * 128 * LDW / 2; i += 256) d[i] = s[i];
    }
    if (tid < 128) s_b1[tid] = b1[tid];

    const int base = blockIdx.x * 128;
    for (int i = tid; i < 128 * 32; i += 256) {
        int r = i >> 5, c4 = (i & 31) * 4;
        float4 v = make_float4(0.f, 0.f, 0.f, 0.f);
        int node = base + r;
        if (node < Nnodes) v = *(const float4*)(nfeat + (size_t)node * 128 + c4);
        __nv_bfloat16 h, l;
        bsplit(v.x, h, l); Ah[r * LDW + c4]     = h; Al[r * LDW + c4]     = l;
        bsplit(v.y, h, l); Ah[r * LDW + c4 + 1] = h; Al[r * LDW + c4 + 1] = l;
        bsplit(v.z, h, l); Ah[r * LDW + c4 + 2] = h; Al[r * LDW + c4 + 2] = l;
        bsplit(v.w, h, l); Ah[r * LDW + c4 + 3] = h; Al[r * LDW + c4 + 3] = l;
    }
    __syncthreads();

    const int warp = tid >> 5, lane = tid & 31, g = lane >> 2, t = lane & 3;
    const int mbase = (warp >> 1) * 32, nbase = (warp & 1) * 64;

    for (int half = 0; half < 2; half++) {
        float acc[2][8][4];
        zero_acc(acc);
        gemm_tile(Ah, Al,
                  Wsm + (half * 2)     * 128 * LDW,
                  Wsm + (half * 2 + 1) * 128 * LDW,
                  acc, mbase, nbase, g, t);
        #pragma unroll
        for (int mi = 0; mi < 2; mi++) {
            int r0 = mbase + mi * 16 + g;
            int n0 = base + r0, n1 = n0 + 8;
            #pragma unroll
            for (int ni = 0; ni < 8; ni++) {
                int col = nbase + ni * 8 + t * 2;
                float bx = half ? s_b1[col]     : 0.f;
                float by = half ? s_b1[col + 1] : 0.f;
                if (n0 < Nnodes) {
                    float2 v = {acc[mi][ni][0] + bx, acc[mi][ni][1] + by};
                    *(float2*)(g_P + (size_t)n0 * 256 + half * 128 + col) = v;
                }
                if (n1 < Nnodes) {
                    float2 v = {acc[mi][ni][2] + bx, acc[mi][ni][3] + by};
                    *(float2*)(g_P + (size_t)n1 * 256 + half * 128 + col) = v;
                }
            }
        }
    }
}

// ---------------------------------------------------------------------------
// Kernel 2: persistent fused edge pipeline.
// ---------------------------------------------------------------------------
__global__ __launch_bounds__(256, 1)
void edge_kernel(const float* __restrict__ efeat,
                 const int* __restrict__ src_idx, const int* __restrict__ dst_idx,
                 const float* __restrict__ b2, const float* __restrict__ ln_g,
                 const float* __restrict__ ln_b, float* __restrict__ out, int E)
{
    extern __shared__ char sm[];
    __nv_bfloat16* Wsm = (__nv_bfloat16*)(sm + SM_W0);
    __nv_bfloat16* Ah  = (__nv_bfloat16*)(sm + SM_ACT);
    __nv_bfloat16* Al  = (__nv_bfloat16*)(sm + SM_ACT_LO);
    float* s_O   = (float*)(sm + SM_ACT);      // reuses act region after GEMM2
    int*   s_src = (int*)(sm + SM_IDX_S);
    int*   s_dst = (int*)(sm + SM_IDX_D);
    float* s_b2  = (float*)(sm + SM_B2);
    float* s_g   = (float*)(sm + SM_G);
    float* s_b   = (float*)(sm + SM_BETA);
    const int tid = threadIdx.x;

    {   // weights -> smem (once per CTA, persistent)
        const uint32_t* s = (const uint32_t*)g_Wedge;
        uint32_t* d = (uint32_t*)Wsm;
        for (int i = tid; i < 4 * 128 * LDW / 2; i += 256) d[i] = s[i];
    }
    if (tid < 128) { s_b2[tid] = b2[tid]; s_g[tid] = ln_g[tid]; s_b[tid] = ln_b[tid]; }

    const int warp = tid >> 5, lane = tid & 31, g = lane >> 2, t = lane & 3;
    const int mbase = (warp >> 1) * 32, nbase = (warp & 1) * 64;
    const int ntiles = (E + 127) / 128;

    for (int tile = blockIdx.x; tile < ntiles; tile += gridDim.x) {
        const int base = tile * 128;
        __syncthreads();  // prev-iter LN done reading s_O; weight copy visible (1st iter)

        if (tid < 128) {
            int e = base + tid;
            s_src[tid] = (e < E) ? src_idx[e] : 0;
            s_dst[tid] = (e < E) ? dst_idx[e] : 0;
        }
        for (int i = tid; i < 128 * 32; i += 256) {
            int r = i >> 5, c4 = (i & 31) * 4;
            int e = base + r;
            float4 v = make_float4(0.f, 0.f, 0.f, 0.f);
            if (e < E) v = *(const float4*)(efeat + (size_t)e * 128 + c4);
            __nv_bfloat16 h, l;
            bsplit(v.x, h, l); Ah[r * LDW + c4]     = h; Al[r * LDW + c4]     = l;
            bsplit(v.y, h, l); Ah[r * LDW + c4 + 1] = h; Al[r * LDW + c4 + 1] = l;
            bsplit(v.z, h, l); Ah[r * LDW + c4 + 2] = h; Al[r * LDW + c4 + 2] = l;
            bsplit(v.w, h, l); Ah[r * LDW + c4 + 3] = h; Al[r * LDW + c4 + 3] = l;
        }
        __syncthreads();

        // GEMM1: efeat @ We^T
        float acc[2][8][4];
        zero_acc(acc);
        gemm_tile(Ah, Al, Wsm, Wsm + 128 * LDW, acc, mbase, nbase, g, t);
        __syncthreads();  // all warps done reading Ah/Al

        // Epilogue 1: gather node projections, SiLU, re-split into Ah/Al as hidden
        #pragma unroll
        for (int mi = 0; mi < 2; mi++) {
            int r0 = mbase + mi * 16 + g, r1 = r0 + 8;
            const float* Ps0 = g_P + (size_t)s_src[r0] * 256;
            const float* Pd0 = g_P + (size_t)s_dst[r0] * 256 + 128;
            const float* Ps1 = g_P + (size_t)s_src[r1] * 256;
            const float* Pd1 = g_P + (size_t)s_dst[r1] * 256 + 128;
            #pragma unroll
            for (int ni = 0; ni < 8; ni++) {
                int col = nbase + ni * 8 + t * 2;
                float2 a = *(const float2*)(Ps0 + col);
                float2 b = *(const float2*)(Pd0 + col);
                float2 c = *(const float2*)(Ps1 + col);
                float2 d = *(const float2*)(Pd1 + col);
                float x0 = acc[mi][ni][0] + a.x + b.x;
                float x1 = acc[mi][ni][1] + a.y + b.y;
                float x2 = acc[mi][ni][2] + c.x + d.x;
                float x3 = acc[mi][ni][3] + c.y + d.y;
                x0 = x0 / (1.f + __expf(-x0));
                x1 = x1 / (1.f + __expf(-x1));
                x2 = x2 / (1.f + __expf(-x2));
                x3 = x3 / (1.f + __expf(-x3));
                __nv_bfloat16 h0, l0, h1, l1;
                __nv_bfloat162 hh, ll;
                bsplit(x0, h0, l0); bsplit(x1, h1, l1);
                hh.x = h0; hh.y = h1; *(__nv_bfloat162*)(Ah + r0 * LDW + col) = hh;
                ll.x = l0; ll.y = l1; *(__nv_bfloat162*)(Al + r0 * LDW + col) = ll;
                bsplit(x2, h0, l0); bsplit(x3, h1, l1);
                hh.x = h0; hh.y = h1; *(__nv_bfloat162*)(Ah + r1 * LDW + col) = hh;
                ll.x = l0; ll.y = l1; *(__nv_bfloat162*)(Al + r1 * LDW + col) = ll;
            }
        }
        __syncthreads();

        // GEMM2: hidden @ W2^T
        zero_acc(acc);
        gemm_tile(Ah, Al, Wsm + 2 * 128 * LDW, Wsm + 3 * 128 * LDW, acc, mbase, nbase, g, t);
        __syncthreads();  // all warps done reading hidden -> reuse region as s_O

        // Epilogue 2: + b2, stage fp32 for LayerNorm
        #pragma unroll
        for (int mi = 0; mi < 2; mi++) {
            int r0 = mbase + mi * 16 + g, r1 = r0 + 8;
            #pragma unroll
            for (int ni = 0; ni < 8; ni++) {
                int col = nbase + ni * 8 + t * 2;
                s_O[r0 * LDO + col]     = acc[mi][ni][0] + s_b2[col];
                s_O[r0 * LDO + col + 1] = acc[mi][ni][1] + s_b2[col + 1];
                s_O[r1 * LDO + col]     = acc[mi][ni][2] + s_b2[col];
                s_O[r1 * LDO + col + 1] = acc[mi][ni][3] + s_b2[col + 1];
            }
        }
        __syncthreads();

        // LayerNorm + store: each warp owns 16 rows
        for (int rr = 0; rr < 16; rr++) {
            int r = warp * 16 + rr;
            float x0 = s_O[r * LDO + lane];
            float x1 = s_O[r * LDO + lane + 32];
            float x2 = s_O[r * LDO + lane + 64];
            float x3 = s_O[r * LDO + lane + 96];
            float s  = x0 + x1 + x2 + x3;
            float s2 = x0 * x0 + x1 * x1 + x2 * x2 + x3 * x3;
            #pragma unroll
            for (int o = 16; o; o >>= 1) {
                s  += __shfl_xor_sync(0xffffffffu, s,  o);
                s2 += __shfl_xor_sync(0xffffffffu, s2, o);
            }
            float mean = s * (1.f / 128.f);
            float var  = s2 * (1.f / 128.f) - mean * mean;
            float rstd = rsqrtf(var + 1e-5f);
            int e = base + r;
            if (e < E) {
                float* po = out + (size_t)e * 128;
                po[lane]      = (x0 - mean) * rstd * s_g[lane]      + s_b[lane];
                po[lane + 32] = (x1 - mean) * rstd * s_g[lane + 32] + s_b[lane + 32];
                po[lane + 64] = (x2 - mean) * rstd * s_g[lane + 64] + s_b[lane + 64];
                po[lane + 96] = (x3 - mean) * rstd * s_g[lane + 96] + s_b[lane + 96];
            }
        }
    }
}

// ---------------------------------------------------------------------------
extern "C" void kernel_launch(void* const* d_in, const int* in_sizes, int n_in,
                              void* d_out, int out_size)
{
    const float* efeat   = (const float*)d_in[0];
    const float* nfeat   = (const float*)d_in[1];
    const int*   src_idx = (const int*)d_in[2];
    const int*   dst_idx = (const int*)d_in[3];
    const float* w_efeat = (const float*)d_in[4];
    const float* w_src   = (const float*)d_in[5];
    const float* w_dst   = (const float*)d_in[6];
    const float* b1      = (const float*)d_in[7];
    const float* w2      = (const float*)d_in[8];
    const float* b2      = (const float*)d_in[9];
    const float* ln_g    = (const float*)d_in[10];
    const float* ln_b    = (const float*)d_in[11];
    float* out = (float*)d_out;

    const int E = in_sizes[2];        // src_idx element count
    const int N = in_sizes[1] / 128;  // nfeat elements / SF

    cudaFuncSetAttribute(node_proj_kernel, cudaFuncAttributeMaxDynamicSharedMemorySize, NODE_SMEM);
    cudaFuncSetAttribute(edge_kernel,      cudaFuncAttributeMaxDynamicSharedMemorySize, EDGE_SMEM);

    prep_weights<<<4, 256>>>(w_efeat, w2, w_src, w_dst);

    int ntiles_n = (N + 127) / 128;
    node_proj_kernel<<<ntiles_n, 256, NODE_SMEM>>>(nfeat, b1, N);

    int nsm = 148;
    cudaDeviceGetAttribute(&nsm, cudaDevAttrMultiProcessorCount, 0);
    edge_kernel<<<nsm, 256, EDGE_SMEM>>>(efeat, src_idx, dst_idx, b2, ln_g, ln_b, out, E);
}

// round 5
// speedup vs baseline: 1.1236x; 1.1236x over previous
#include <cuda_runtime.h>
#include <cuda_bf16.h>
#include <cstdint>

// ===========================================================================
// MeshGraphEdgeMLPSum:
//   out = LN( silu(efeat@We^T + Psrc[src] + Pdst[dst]) @ W2^T + b2 )
//   Psrc = nfeat@Wsrc^T ; Pdst = nfeat@Wdst^T + b1
// Toolchain lowers to PTX target sm_103 (no 'a') -> tcgen05 unavailable.
// Path: legacy HMMA mma.sync.m16n8k16.bf16, 2-way bf16 split (3 terms),
// ldmatrix.x4 fragment loads, register-resident LayerNorm epilogue.
// ===========================================================================

#define LDW 136   // padded bf16 row stride: 272B -> ldmatrix conflict-free

// ------------------------- scratch globals --------------------------------
__device__ __nv_bfloat16 g_Wedge[4][128 * LDW];    // We_hi, We_lo, W2_hi, W2_lo
__device__ __nv_bfloat16 g_Wnode[4][128 * LDW];    // Ws_hi, Ws_lo, Wd_hi, Wd_lo
__device__ float         g_P[50048 * 256];         // [node][0:128]=src, [128:256]=dst+b1

// ------------------------- helpers ----------------------------------------
__device__ __forceinline__ void bsplit(float x, __nv_bfloat16& h, __nv_bfloat16& l) {
    h = __float2bfloat16(x);
    l = __float2bfloat16(x - __bfloat162float(h));
}

__device__ __forceinline__ uint32_t smem_u32(const void* p) {
    uint32_t a;
    asm("{ .reg .u64 t; cvta.to.shared.u64 t, %1; cvt.u32.u64 %0, t; }" : "=r"(a) : "l"(p));
    return a;
}

__device__ __forceinline__ void ldsm4(uint32_t* r, uint32_t addr) {
    asm volatile("ldmatrix.sync.aligned.m8n8.x4.shared.b16 {%0,%1,%2,%3}, [%4];"
        : "=r"(r[0]), "=r"(r[1]), "=r"(r[2]), "=r"(r[3]) : "r"(addr));
}

__device__ __forceinline__ void mma16816(float* c, const uint32_t* a, uint32_t b0, uint32_t b1) {
    asm volatile(
        "mma.sync.aligned.m16n8k16.row.col.f32.bf16.bf16.f32 "
        "{%0,%1,%2,%3}, {%4,%5,%6,%7}, {%8,%9}, {%0,%1,%2,%3};\n"
        : "+f"(c[0]), "+f"(c[1]), "+f"(c[2]), "+f"(c[3])
        : "r"(a[0]), "r"(a[1]), "r"(a[2]), "r"(a[3]), "r"(b0), "r"(b1));
}

// C[128x128] += A * W^T (3-term bf16 split), fragments via ldmatrix.x4.
// Warp grid 4(M)x2(N): warp tile 32x64. acc[2][8][4]. Layout identical to the
// verified scalar-LDS version (a0: m=lane>>2, k=(lane&3)*2 ; b0: n=lane>>2, k=(lane&3)*2).
__device__ __forceinline__ void gemm_tile(
    const __nv_bfloat16* Ah, const __nv_bfloat16* Al,
    const __nv_bfloat16* Wh, const __nv_bfloat16* Wl,
    float acc[2][8][4], int mbase, int nbase, int lane)
{
    // A tile addresses: matrix0 rows0-7/k0-7, m1 rows8-15/k0-7, m2 rows0-7/k8-15, m3 rows8-15/k8-15
    const int rowA = lane & 15;
    const int colA = (lane >> 4) << 3;
    uint32_t aH = smem_u32(Ah) + (uint32_t)(((mbase + rowA) * LDW + colA) * 2);
    uint32_t aL = smem_u32(Al) + (uint32_t)(((mbase + rowA) * LDW + colA) * 2);
    // B pair-of-ni addresses: m0 n0-7/k0-7, m1 n0-7/k8-15, m2 n8-15/k0-7, m3 n8-15/k8-15
    const int rowB = (lane & 7) + ((lane & 16) >> 1);
    const int colB = lane & 8;
    uint32_t bH = smem_u32(Wh) + (uint32_t)(((nbase + rowB) * LDW + colB) * 2);
    uint32_t bL = smem_u32(Wl) + (uint32_t)(((nbase + rowB) * LDW + colB) * 2);

    const uint32_t MI_STRIDE = 16 * LDW * 2;  // bytes between A mi tiles / B ni pairs

    #pragma unroll
    for (int k0 = 0; k0 < 128; k0 += 16) {
        uint32_t ah[2][4], al[2][4], bh[4][4], bl[4][4];
        #pragma unroll
        for (int mi = 0; mi < 2; mi++) {
            ldsm4(ah[mi], aH + mi * MI_STRIDE + k0 * 2);
            ldsm4(al[mi], aL + mi * MI_STRIDE + k0 * 2);
        }
        #pragma unroll
        for (int p = 0; p < 4; p++) {
            ldsm4(bh[p], bH + p * MI_STRIDE + k0 * 2);
            ldsm4(bl[p], bL + p * MI_STRIDE + k0 * 2);
        }
        // bh[p] = { b0(ni=2p), b1(ni=2p), b0(ni=2p+1), b1(ni=2p+1) }
        #pragma unroll
        for (int ni = 0; ni < 8; ni++)
            #pragma unroll
            for (int mi = 0; mi < 2; mi++)
                mma16816(acc[mi][ni], ah[mi], bh[ni >> 1][(ni & 1) * 2], bh[ni >> 1][(ni & 1) * 2 + 1]);
        #pragma unroll
        for (int ni = 0; ni < 8; ni++)
            #pragma unroll
            for (int mi = 0; mi < 2; mi++)
                mma16816(acc[mi][ni], ah[mi], bl[ni >> 1][(ni & 1) * 2], bl[ni >> 1][(ni & 1) * 2 + 1]);
        #pragma unroll
        for (int ni = 0; ni < 8; ni++)
            #pragma unroll
            for (int mi = 0; mi < 2; mi++)
                mma16816(acc[mi][ni], al[mi], bh[ni >> 1][(ni & 1) * 2], bh[ni >> 1][(ni & 1) * 2 + 1]);
    }
}

__device__ __forceinline__ void zero_acc(float acc[2][8][4]) {
    #pragma unroll
    for (int mi = 0; mi < 2; mi++)
        #pragma unroll
        for (int ni = 0; ni < 8; ni++)
            #pragma unroll
            for (int j = 0; j < 4; j++)
                acc[mi][ni][j] = 0.f;
}

// ------------------------- kernel 0: weight prep --------------------------
// 64 blocks: mat = bx & 3, slice = bx >> 2 covers 8 rows each.
__global__ void prep_weights(const float* we, const float* w2,
                             const float* ws, const float* wd)
{
    int mat = blockIdx.x & 3, slice = blockIdx.x >> 2;
    const float* src = (mat == 0) ? we : (mat == 1) ? w2 : (mat == 2) ? ws : wd;
    __nv_bfloat16* dh = (mat < 2) ? g_Wedge[2 * mat]     : g_Wnode[2 * (mat - 2)];
    __nv_bfloat16* dl = (mat < 2) ? g_Wedge[2 * mat + 1] : g_Wnode[2 * (mat - 2) + 1];
    int r0 = slice * 8;
    for (int i = threadIdx.x; i < 8 * 128; i += blockDim.x) {
        int r = r0 + (i >> 7), c = i & 127;
        __nv_bfloat16 h, l;
        bsplit(src[r * 128 + c], h, l);
        dh[r * LDW + c] = h;
        dl[r * LDW + c] = l;
    }
}

// ------------------------- kernel 1: node projections ---------------------
#define NSM_W0     0
#define NSM_ACT    (4 * 128 * LDW * 2)             // 139264
#define NSM_ACT_LO (NSM_ACT + 128 * LDW * 2)       // 174080
#define NSM_B1     (NSM_ACT + 2 * 128 * LDW * 2)   // 208896
#define NODE_SMEM  (NSM_B1 + 512)                  // 209408

__global__ __launch_bounds__(256, 1)
void node_proj_kernel(const float* __restrict__ nfeat, const float* __restrict__ b1, int Nnodes)
{
    extern __shared__ char sm[];
    __nv_bfloat16* Wsm = (__nv_bfloat16*)(sm + NSM_W0);
    __nv_bfloat16* Ah  = (__nv_bfloat16*)(sm + NSM_ACT);
    __nv_bfloat16* Al  = (__nv_bfloat16*)(sm + NSM_ACT_LO);
    float* s_b1 = (float*)(sm + NSM_B1);
    const int tid = threadIdx.x;

    {
        const uint4* s = (const uint4*)g_Wnode;
        uint4* d = (uint4*)Wsm;
        for (int i = tid; i < 4 * 128 * LDW * 2 / 16; i += 256) d[i] = s[i];
    }
    if (tid < 128) s_b1[tid] = b1[tid];

    const int base = blockIdx.x * 128;
    for (int i = tid; i < 128 * 32; i += 256) {
        int r = i >> 5, c4 = (i & 31) * 4;
        float4 v = make_float4(0.f, 0.f, 0.f, 0.f);
        int node = base + r;
        if (node < Nnodes) v = *(const float4*)(nfeat + (size_t)node * 128 + c4);
        __nv_bfloat16 h, l;
        bsplit(v.x, h, l); Ah[r * LDW + c4]     = h; Al[r * LDW + c4]     = l;
        bsplit(v.y, h, l); Ah[r * LDW + c4 + 1] = h; Al[r * LDW + c4 + 1] = l;
        bsplit(v.z, h, l); Ah[r * LDW + c4 + 2] = h; Al[r * LDW + c4 + 2] = l;
        bsplit(v.w, h, l); Ah[r * LDW + c4 + 3] = h; Al[r * LDW + c4 + 3] = l;
    }
    __syncthreads();

    const int warp = tid >> 5, lane = tid & 31, g = lane >> 2, t = lane & 3;
    const int mbase = (warp >> 1) * 32, nbase = (warp & 1) * 64;

    for (int half = 0; half < 2; half++) {
        float acc[2][8][4];
        zero_acc(acc);
        gemm_tile(Ah, Al,
                  Wsm + (half * 2)     * 128 * LDW,
                  Wsm + (half * 2 + 1) * 128 * LDW,
                  acc, mbase, nbase, lane);
        #pragma unroll
        for (int mi = 0; mi < 2; mi++) {
            int r0 = mbase + mi * 16 + g;
            int n0 = base + r0, n1 = n0 + 8;
            #pragma unroll
            for (int ni = 0; ni < 8; ni++) {
                int col = nbase + ni * 8 + t * 2;
                float bx = half ? s_b1[col]     : 0.f;
                float by = half ? s_b1[col + 1] : 0.f;
                if (n0 < Nnodes) {
                    float2 v = {acc[mi][ni][0] + bx, acc[mi][ni][1] + by};
                    *(float2*)(g_P + (size_t)n0 * 256 + half * 128 + col) = v;
                }
                if (n1 < Nnodes) {
                    float2 v = {acc[mi][ni][2] + bx, acc[mi][ni][3] + by};
                    *(float2*)(g_P + (size_t)n1 * 256 + half * 128 + col) = v;
                }
            }
        }
    }
}

// ------------------------- kernel 2: persistent fused edge pipeline -------
#define ESM_W      0
#define ESM_ACT    (4 * 128 * LDW * 2)             // 139264
#define ESM_ACT_LO (ESM_ACT + 128 * LDW * 2)       // 174080
#define ESM_RED    (ESM_ACT + 2 * 128 * LDW * 2)   // 208896 : float2 s_red[256] = 2048
#define ESM_IDX_S  (ESM_RED + 2048)                // 210944
#define ESM_IDX_D  (ESM_IDX_S + 512)               // 211456
#define ESM_B2     (ESM_IDX_D + 512)               // 211968
#define ESM_G      (ESM_B2 + 512)                  // 212480
#define ESM_BETA   (ESM_G + 512)                   // 212992
#define EDGE_SMEM  (ESM_BETA + 512)                // 213504

__global__ __launch_bounds__(256, 1)
void edge_kernel(const float* __restrict__ efeat,
                 const int* __restrict__ src_idx, const int* __restrict__ dst_idx,
                 const float* __restrict__ b2, const float* __restrict__ ln_g,
                 const float* __restrict__ ln_b, float* __restrict__ out, int E)
{
    extern __shared__ char sm[];
    __nv_bfloat16* Wsm = (__nv_bfloat16*)(sm + ESM_W);
    __nv_bfloat16* Ah  = (__nv_bfloat16*)(sm + ESM_ACT);
    __nv_bfloat16* Al  = (__nv_bfloat16*)(sm + ESM_ACT_LO);
    float2* s_red = (float2*)(sm + ESM_RED);       // [row*2 + nhalf] -> (sum, sumsq)
    int*   s_src = (int*)(sm + ESM_IDX_S);
    int*   s_dst = (int*)(sm + ESM_IDX_D);
    float* s_b2  = (float*)(sm + ESM_B2);
    float* s_g   = (float*)(sm + ESM_G);
    float* s_bt  = (float*)(sm + ESM_BETA);
    const int tid = threadIdx.x;

    {   // weights -> smem once (persistent CTA)
        const uint4* s = (const uint4*)g_Wedge;
        uint4* d = (uint4*)Wsm;
        for (int i = tid; i < 4 * 128 * LDW * 2 / 16; i += 256) d[i] = s[i];
    }
    if (tid < 128) { s_b2[tid] = b2[tid]; s_g[tid] = ln_g[tid]; s_bt[tid] = ln_b[tid]; }

    const int warp = tid >> 5, lane = tid & 31, g = lane >> 2, t = lane & 3;
    const int mbase = (warp >> 1) * 32, nbase = (warp & 1) * 64;
    const int ntiles = (E + 127) >> 7;

    for (int tile = blockIdx.x; tile < ntiles; tile += gridDim.x) {
        const int base = tile << 7;
        __syncthreads();  // all warps done with prev tile's smem (GEMM2 ldsm, s_red)

        if (tid < 128) {
            int e = base + tid;
            s_src[tid] = (e < E) ? src_idx[e] : 0;
            s_dst[tid] = (e < E) ? dst_idx[e] : 0;
        }
        #pragma unroll 4
        for (int i = tid; i < 128 * 32; i += 256) {
            int r = i >> 5, c4 = (i & 31) * 4;
            int e = base + r;
            float4 v = make_float4(0.f, 0.f, 0.f, 0.f);
            if (e < E) v = *(const float4*)(efeat + (size_t)e * 128 + c4);
            __nv_bfloat16 h, l;
            bsplit(v.x, h, l); Ah[r * LDW + c4]     = h; Al[r * LDW + c4]     = l;
            bsplit(v.y, h, l); Ah[r * LDW + c4 + 1] = h; Al[r * LDW + c4 + 1] = l;
            bsplit(v.z, h, l); Ah[r * LDW + c4 + 2] = h; Al[r * LDW + c4 + 2] = l;
            bsplit(v.w, h, l); Ah[r * LDW + c4 + 3] = h; Al[r * LDW + c4 + 3] = l;
        }
        __syncthreads();

        // GEMM1: efeat @ We^T
        float acc[2][8][4];
        zero_acc(acc);
        gemm_tile(Ah, Al, Wsm, Wsm + 128 * LDW, acc, mbase, nbase, lane);

        // Gather node projections (before barrier: warp-local regs only)
        // then SiLU + re-split. Writes to Ah/Al must wait for all warps' GEMM1 reads.
        float xs[2][8][4];
        #pragma unroll
        for (int mi = 0; mi < 2; mi++) {
            int r0 = mbase + mi * 16 + g, r1 = r0 + 8;
            const float* Ps0 = g_P + (size_t)s_src[r0] * 256;
            const float* Pd0 = g_P + (size_t)s_dst[r0] * 256 + 128;
            const float* Ps1 = g_P + (size_t)s_src[r1] * 256;
            const float* Pd1 = g_P + (size_t)s_dst[r1] * 256 + 128;
            #pragma unroll
            for (int ni = 0; ni < 8; ni++) {
                int col = nbase + ni * 8 + t * 2;
                float2 a = *(const float2*)(Ps0 + col);
                float2 b = *(const float2*)(Pd0 + col);
                float2 c = *(const float2*)(Ps1 + col);
                float2 d = *(const float2*)(Pd1 + col);
                float x0 = acc[mi][ni][0] + a.x + b.x;
                float x1 = acc[mi][ni][1] + a.y + b.y;
                float x2 = acc[mi][ni][2] + c.x + d.x;
                float x3 = acc[mi][ni][3] + c.y + d.y;
                xs[mi][ni][0] = x0 / (1.f + __expf(-x0));
                xs[mi][ni][1] = x1 / (1.f + __expf(-x1));
                xs[mi][ni][2] = x2 / (1.f + __expf(-x2));
                xs[mi][ni][3] = x3 / (1.f + __expf(-x3));
            }
        }
        __syncthreads();  // all warps finished GEMM1 ldsm of Ah/Al

        // hidden -> Ah/Al (bf16 split), same fragment positions
        #pragma unroll
        for (int mi = 0; mi < 2; mi++) {
            int r0 = mbase + mi * 16 + g, r1 = r0 + 8;
            #pragma unroll
            for (int ni = 0; ni < 8; ni++) {
                int col = nbase + ni * 8 + t * 2;
                __nv_bfloat16 h0, l0, h1, l1;
                __nv_bfloat162 hh, ll;
                bsplit(xs[mi][ni][0], h0, l0); bsplit(xs[mi][ni][1], h1, l1);
                hh.x = h0; hh.y = h1; *(__nv_bfloat162*)(Ah + r0 * LDW + col) = hh;
                ll.x = l0; ll.y = l1; *(__nv_bfloat162*)(Al + r0 * LDW + col) = ll;
                bsplit(xs[mi][ni][2], h0, l0); bsplit(xs[mi][ni][3], h1, l1);
                hh.x = h0; hh.y = h1; *(__nv_bfloat162*)(Ah + r1 * LDW + col) = hh;
                ll.x = l0; ll.y = l1; *(__nv_bfloat162*)(Al + r1 * LDW + col) = ll;
            }
        }
        __syncthreads();

        // GEMM2: hidden @ W2^T
        zero_acc(acc);
        gemm_tile(Ah, Al, Wsm + 2 * 128 * LDW, Wsm + 3 * 128 * LDW, acc, mbase, nbase, lane);

        // Epilogue: +b2, per-row partial sums -> smem combine -> normalize from regs
        #pragma unroll
        for (int mi = 0; mi < 2; mi++) {
            #pragma unroll
            for (int hr = 0; hr < 2; hr++) {
                float s = 0.f, s2 = 0.f;
                #pragma unroll
                for (int ni = 0; ni < 8; ni++) {
                    int col = nbase + ni * 8 + t * 2;
                    float x0 = acc[mi][ni][hr * 2]     + s_b2[col];
                    float x1 = acc[mi][ni][hr * 2 + 1] + s_b2[col + 1];
                    acc[mi][ni][hr * 2]     = x0;
                    acc[mi][ni][hr * 2 + 1] = x1;
                    s += x0 + x1;
                    s2 += x0 * x0 + x1 * x1;
                }
                s  += __shfl_xor_sync(0xffffffffu, s, 1);
                s2 += __shfl_xor_sync(0xffffffffu, s2, 1);
                s  += __shfl_xor_sync(0xffffffffu, s, 2);
                s2 += __shfl_xor_sync(0xffffffffu, s2, 2);
                if (t == 0) {
                    int r = mbase + mi * 16 + g + hr * 8;
                    s_red[r * 2 + (nbase >> 6)] = make_float2(s, s2);
                }
            }
        }
        __syncthreads();

        #pragma unroll
        for (int mi = 0; mi < 2; mi++) {
            #pragma unroll
            for (int hr = 0; hr < 2; hr++) {
                int r = mbase + mi * 16 + g + hr * 8;
                float2 p0 = s_red[r * 2], p1 = s_red[r * 2 + 1];
                float s = p0.x + p1.x, s2 = p0.y + p1.y;
                float mean = s * (1.f / 128.f);
                float var  = s2 * (1.f / 128.f) - mean * mean;
                float rstd = rsqrtf(var + 1e-5f);
                int e = base + r;
                if (e < E) {
                    float* po = out + (size_t)e * 128;
                    #pragma unroll
                    for (int ni = 0; ni < 8; ni++) {
                        int col = nbase + ni * 8 + t * 2;
                        float2 v;
                        v.x = (acc[mi][ni][hr * 2]     - mean) * rstd * s_g[col]     + s_bt[col];
                        v.y = (acc[mi][ni][hr * 2 + 1] - mean) * rstd * s_g[col + 1] + s_bt[col + 1];
                        *(float2*)(po + col) = v;
                    }
                }
            }
        }
    }
}

// ---------------------------------------------------------------------------
extern "C" void kernel_launch(void* const* d_in, const int* in_sizes, int n_in,
                              void* d_out, int out_size)
{
    const float* efeat   = (const float*)d_in[0];
    const float* nfeat   = (const float*)d_in[1];
    const int*   src_idx = (const int*)d_in[2];
    const int*   dst_idx = (const int*)d_in[3];
    const float* w_efeat = (const float*)d_in[4];
    const float* w_src   = (const float*)d_in[5];
    const float* w_dst   = (const float*)d_in[6];
    const float* b1      = (const float*)d_in[7];
    const float* w2      = (const float*)d_in[8];
    const float* b2      = (const float*)d_in[9];
    const float* ln_g    = (const float*)d_in[10];
    const float* ln_b    = (const float*)d_in[11];
    float* out = (float*)d_out;

    const int E = in_sizes[2];
    const int N = in_sizes[1] / 128;

    cudaFuncSetAttribute(node_proj_kernel, cudaFuncAttributeMaxDynamicSharedMemorySize, NODE_SMEM);
    cudaFuncSetAttribute(edge_kernel,      cudaFuncAttributeMaxDynamicSharedMemorySize, EDGE_SMEM);

    prep_weights<<<64, 256>>>(w_efeat, w2, w_src, w_dst);

    int ntiles_n = (N + 127) / 128;
    node_proj_kernel<<<ntiles_n, 256, NODE_SMEM>>>(nfeat, b1, N);

    int nsm = 148;
    cudaDeviceGetAttribute(&nsm, cudaDevAttrMultiProcessorCount, 0);
    edge_kernel<<<nsm, 256, EDGE_SMEM>>>(efeat, src_idx, dst_idx, b2, ln_g, ln_b, out, E);
}

// round 7
// speedup vs baseline: 1.3686x; 1.2181x over previous
#include <cuda_runtime.h>
#include <cuda_fp16.h>
#include <cstdint>

// ===========================================================================
// MeshGraphEdgeMLPSum — single persistent kernel, 3 phases w/ grid barriers:
//   P0: split all 4 weight matrices into fp16 hi/lo (staged in gmem)
//   P1: node projections  P[n] = [nfeat@Ws^T | nfeat@Wd^T + b1]
//   P2: edge pipeline      out = LN( silu(ef@We^T + Ps[src]+Pd[dst]) @ W2^T + b2 )
// All GEMMs: fp16 2-term (act rounded once, W = Wh + Wl), fp32 accumulate,
// legacy mma.sync.m16n8k16.f16 + ldmatrix.x4 (tcgen05 unavailable: ptx target
// is sm_103 without 'a').  Predicted rel_err ~2.5e-4 (<1e-3).
// ===========================================================================

#define LDW 136   // padded fp16 row stride (272 B): ldmatrix conflict-free

// ------------------------- globals ----------------------------------------
__device__ __half g_W[8][128 * LDW];   // We_h,We_l,W2_h,W2_l,Ws_h,Ws_l,Wd_h,Wd_l
__device__ float  g_P[50048 * 256];    // [node][0:128]=src proj, [128:256]=dst+b1
__device__ unsigned int g_cnt = 0;     // monotone grid-barrier counter

// ------------------------- smem layout ------------------------------------
#define SM_W     0                       // 4 x 128*LDW fp16 = 139264
#define SM_ACT   139264                  // 128*LDW fp16     =  34816
#define SM_RED   174080                  // float2[256]      =   2048
#define SM_IDXS  176128                  // int[128]
#define SM_IDXD  176640
#define SM_B2    177152
#define SM_G     177664
#define SM_BT    178176
#define SM_B1    178688
#define SMEM_SZ  179200

// ------------------------- helpers ----------------------------------------
__device__ __forceinline__ uint32_t smem_u32(const void* p) {
    uint32_t a;
    asm("{ .reg .u64 t; cvta.to.shared.u64 t, %1; cvt.u32.u64 %0, t; }" : "=r"(a) : "l"(p));
    return a;
}

__device__ __forceinline__ void ldsm4(uint32_t* r, uint32_t addr) {
    asm volatile("ldmatrix.sync.aligned.m8n8.x4.shared.b16 {%0,%1,%2,%3}, [%4];"
        : "=r"(r[0]), "=r"(r[1]), "=r"(r[2]), "=r"(r[3]) : "r"(addr));
}

__device__ __forceinline__ void mma_f16(float* c, const uint32_t* a, uint32_t b0, uint32_t b1) {
    asm volatile(
        "mma.sync.aligned.m16n8k16.row.col.f32.f16.f16.f32 "
        "{%0,%1,%2,%3}, {%4,%5,%6,%7}, {%8,%9}, {%0,%1,%2,%3};\n"
        : "+f"(c[0]), "+f"(c[1]), "+f"(c[2]), "+f"(c[3])
        : "r"(a[0]), "r"(a[1]), "r"(a[2]), "r"(a[3]), "r"(b0), "r"(b1));
}

// monotone grid barrier: no reset needed across graph replays
__device__ __forceinline__ void grid_barrier(int nctas) {
    __syncthreads();
    if (threadIdx.x == 0) {
        __threadfence();
        unsigned int t = atomicAdd(&g_cnt, 1u) + 1u;
        unsigned int target = ((t + (unsigned)nctas - 1u) / (unsigned)nctas) * (unsigned)nctas;
        unsigned int cur;
        do {
            asm volatile("ld.acquire.gpu.u32 %0, [%1];" : "=r"(cur) : "l"(&g_cnt));
        } while (cur < target);
    }
    __syncthreads();
}

// acc += A @ (Wh + Wl)^T : fp16 2-term, ldmatrix.x4 fragments.
// Warp grid 4(M)x2(N), warp tile 32x64, acc[2][8][4]; fragment/thread mapping
// identical to the R2-verified scalar layout.
__device__ __forceinline__ void gemm2(
    const __half* A, const __half* Wh, const __half* Wl,
    float acc[2][8][4], int mbase, int nbase, int lane)
{
    const int rowA = lane & 15;
    const int colA = (lane >> 4) << 3;
    uint32_t aA = smem_u32(A) + (uint32_t)(((mbase + rowA) * LDW + colA) * 2);
    const int rowB = (lane & 7) + ((lane & 16) >> 1);
    const int colB = lane & 8;
    uint32_t aBh = smem_u32(Wh) + (uint32_t)(((nbase + rowB) * LDW + colB) * 2);
    uint32_t aBl = smem_u32(Wl) + (uint32_t)(((nbase + rowB) * LDW + colB) * 2);
    const uint32_t MI = 16 * LDW * 2;

    #pragma unroll
    for (int k0 = 0; k0 < 128; k0 += 16) {
        uint32_t a0[4], a1[4], bh[4][4], bl[4][4];
        ldsm4(a0, aA + k0 * 2);
        ldsm4(a1, aA + MI + k0 * 2);
        #pragma unroll
        for (int p = 0; p < 4; p++) {
            ldsm4(bh[p], aBh + p * MI + k0 * 2);
            ldsm4(bl[p], aBl + p * MI + k0 * 2);
        }
        #pragma unroll
        for (int ni = 0; ni < 8; ni++) {
            mma_f16(acc[0][ni], a0, bh[ni >> 1][(ni & 1) * 2], bh[ni >> 1][(ni & 1) * 2 + 1]);
            mma_f16(acc[1][ni], a1, bh[ni >> 1][(ni & 1) * 2], bh[ni >> 1][(ni & 1) * 2 + 1]);
        }
        #pragma unroll
        for (int ni = 0; ni < 8; ni++) {
            mma_f16(acc[0][ni], a0, bl[ni >> 1][(ni & 1) * 2], bl[ni >> 1][(ni & 1) * 2 + 1]);
            mma_f16(acc[1][ni], a1, bl[ni >> 1][(ni & 1) * 2], bl[ni >> 1][(ni & 1) * 2 + 1]);
        }
    }
}

__device__ __forceinline__ void zero_acc(float acc[2][8][4]) {
    #pragma unroll
    for (int mi = 0; mi < 2; mi++)
        #pragma unroll
        for (int ni = 0; ni < 8; ni++)
            #pragma unroll
            for (int j = 0; j < 4; j++)
                acc[mi][ni][j] = 0.f;
}

// ------------------------- the fused persistent kernel --------------------
__global__ __launch_bounds__(256, 1)
void fused_kernel(const float* __restrict__ efeat, const float* __restrict__ nfeat,
                  const int* __restrict__ src_idx, const int* __restrict__ dst_idx,
                  const float* __restrict__ w_efeat, const float* __restrict__ w_src,
                  const float* __restrict__ w_dst,  const float* __restrict__ b1,
                  const float* __restrict__ w2,     const float* __restrict__ b2,
                  const float* __restrict__ ln_g,   const float* __restrict__ ln_b,
                  float* __restrict__ out, int E, int Nn)
{
    extern __shared__ char sm[];
    __half* Wsm   = (__half*)(sm + SM_W);
    __half* Act   = (__half*)(sm + SM_ACT);
    float2* s_red = (float2*)(sm + SM_RED);
    int*    s_src = (int*)(sm + SM_IDXS);
    int*    s_dst = (int*)(sm + SM_IDXD);
    float*  s_b2  = (float*)(sm + SM_B2);
    float*  s_g   = (float*)(sm + SM_G);
    float*  s_bt  = (float*)(sm + SM_BT);
    float*  s_b1  = (float*)(sm + SM_B1);

    const int tid = threadIdx.x;
    const int nctas = gridDim.x;
    const int warp = tid >> 5, lane = tid & 31, g = lane >> 2, t = lane & 3;
    const int mbase = (warp >> 1) * 32, nbase = (warp & 1) * 64;

    // ---------------- phase 0: weight split (fp16 hi/lo) ----------------
    {
        const float* srcs[4] = { w_efeat, w2, w_src, w_dst };
        for (int i = blockIdx.x * 256 + tid; i < 4 * 16384; i += nctas * 256) {
            int mat = i >> 14, idx = i & 16383;
            int r = idx >> 7, c = idx & 127;
            float v = srcs[mat][r * 128 + c];
            __half h = __float2half(v);
            __half l = __float2half(v - __half2float(h));
            g_W[2 * mat][r * LDW + c]     = h;
            g_W[2 * mat + 1][r * LDW + c] = l;
        }
    }
    grid_barrier(nctas);

    // ---------------- phase 1: node projections -------------------------
    {
        // node weights (Ws_h, Ws_l, Wd_h, Wd_l) -> smem
        const uint4* s = (const uint4*)g_W[4];
        uint4* d = (uint4*)Wsm;
        for (int i = tid; i < 4 * 128 * LDW * 2 / 16; i += 256) d[i] = s[i];
        if (tid < 128) s_b1[tid] = b1[tid];
        __syncthreads();

        const int ntile = (Nn + 127) >> 7;
        for (int tile = blockIdx.x; tile < ntile; tile += nctas) {
            const int base = tile << 7;
            __syncthreads();  // prev tile's gemm reads of Act done

            #pragma unroll 4
            for (int i = tid; i < 128 * 32; i += 256) {
                int r = i >> 5, c4 = (i & 31) * 4;
                int node = base + r;
                float4 v = make_float4(0.f, 0.f, 0.f, 0.f);
                if (node < Nn) v = *(const float4*)(nfeat + (size_t)node * 128 + c4);
                __half2 p0 = __floats2half2_rn(v.x, v.y);
                __half2 p1 = __floats2half2_rn(v.z, v.w);
                *(__half2*)(Act + r * LDW + c4)     = p0;
                *(__half2*)(Act + r * LDW + c4 + 2) = p1;
            }
            __syncthreads();

            #pragma unroll
            for (int half = 0; half < 2; half++) {
                float acc[2][8][4];
                zero_acc(acc);
                gemm2(Act, Wsm + (half * 2) * 128 * LDW, Wsm + (half * 2 + 1) * 128 * LDW,
                      acc, mbase, nbase, lane);
                #pragma unroll
                for (int mi = 0; mi < 2; mi++) {
                    int r0 = mbase + mi * 16 + g;
                    int n0 = base + r0, n1 = n0 + 8;
                    #pragma unroll
                    for (int ni = 0; ni < 8; ni++) {
                        int col = nbase + ni * 8 + t * 2;
                        float bx = half ? s_b1[col]     : 0.f;
                        float by = half ? s_b1[col + 1] : 0.f;
                        if (n0 < Nn) {
                            float2 v = {acc[mi][ni][0] + bx, acc[mi][ni][1] + by};
                            *(float2*)(g_P + (size_t)n0 * 256 + half * 128 + col) = v;
                        }
                        if (n1 < Nn) {
                            float2 v = {acc[mi][ni][2] + bx, acc[mi][ni][3] + by};
                            *(float2*)(g_P + (size_t)n1 * 256 + half * 128 + col) = v;
                        }
                    }
                }
            }
        }
    }
    grid_barrier(nctas);

    // ---------------- phase 2: edge pipeline ----------------------------
    {
        // edge weights (We_h, We_l, W2_h, W2_l) -> smem
        const uint4* s = (const uint4*)g_W[0];
        uint4* d = (uint4*)Wsm;
        for (int i = tid; i < 4 * 128 * LDW * 2 / 16; i += 256) d[i] = s[i];
        if (tid < 128) { s_b2[tid] = b2[tid]; s_g[tid] = ln_g[tid]; s_bt[tid] = ln_b[tid]; }

        const int ntiles = (E + 127) >> 7;
        for (int tile = blockIdx.x; tile < ntiles; tile += nctas) {
            const int base = tile << 7;
            __syncthreads();  // prev tile fully consumed (gemm reads, s_red)

            if (tid < 128) {
                int e = base + tid;
                s_src[tid] = (e < E) ? src_idx[e] : 0;
                s_dst[tid] = (e < E) ? dst_idx[e] : 0;
            }
            #pragma unroll 4
            for (int i = tid; i < 128 * 32; i += 256) {
                int r = i >> 5, c4 = (i & 31) * 4;
                int e = base + r;
                float4 v = make_float4(0.f, 0.f, 0.f, 0.f);
                if (e < E) v = *(const float4*)(efeat + (size_t)e * 128 + c4);
                __half2 p0 = __floats2half2_rn(v.x, v.y);
                __half2 p1 = __floats2half2_rn(v.z, v.w);
                *(__half2*)(Act + r * LDW + c4)     = p0;
                *(__half2*)(Act + r * LDW + c4 + 2) = p1;
            }
            __syncthreads();

            // GEMM1: efeat @ We^T
            float acc[2][8][4];
            zero_acc(acc);
            gemm2(Act, Wsm, Wsm + 128 * LDW, acc, mbase, nbase, lane);

            // gather node projections + SiLU, folded into acc (regs only)
            #pragma unroll
            for (int mi = 0; mi < 2; mi++) {
                int r0 = mbase + mi * 16 + g, r1 = r0 + 8;
                const float* Ps0 = g_P + (size_t)s_src[r0] * 256;
                const float* Pd0 = g_P + (size_t)s_dst[r0] * 256 + 128;
                const float* Ps1 = g_P + (size_t)s_src[r1] * 256;
                const float* Pd1 = g_P + (size_t)s_dst[r1] * 256 + 128;
                #pragma unroll
                for (int ni = 0; ni < 8; ni++) {
                    int col = nbase + ni * 8 + t * 2;
                    float2 a = *(const float2*)(Ps0 + col);
                    float2 b = *(const float2*)(Pd0 + col);
                    float2 c = *(const float2*)(Ps1 + col);
                    float2 dd = *(const float2*)(Pd1 + col);
                    float x0 = acc[mi][ni][0] + a.x + b.x;
                    float x1 = acc[mi][ni][1] + a.y + b.y;
                    float x2 = acc[mi][ni][2] + c.x + dd.x;
                    float x3 = acc[mi][ni][3] + c.y + dd.y;
                    acc[mi][ni][0] = x0 / (1.f + __expf(-x0));
                    acc[mi][ni][1] = x1 / (1.f + __expf(-x1));
                    acc[mi][ni][2] = x2 / (1.f + __expf(-x2));
                    acc[mi][ni][3] = x3 / (1.f + __expf(-x3));
                }
            }
            __syncthreads();  // all warps done reading Act (GEMM1)

            // hidden -> Act (single fp16 tile)
            #pragma unroll
            for (int mi = 0; mi < 2; mi++) {
                int r0 = mbase + mi * 16 + g, r1 = r0 + 8;
                #pragma unroll
                for (int ni = 0; ni < 8; ni++) {
                    int col = nbase + ni * 8 + t * 2;
                    *(__half2*)(Act + r0 * LDW + col) =
                        __floats2half2_rn(acc[mi][ni][0], acc[mi][ni][1]);
                    *(__half2*)(Act + r1 * LDW + col) =
                        __floats2half2_rn(acc[mi][ni][2], acc[mi][ni][3]);
                }
            }
            __syncthreads();

            // GEMM2: hidden @ W2^T
            zero_acc(acc);
            gemm2(Act, Wsm + 2 * 128 * LDW, Wsm + 3 * 128 * LDW, acc, mbase, nbase, lane);

            // +b2, per-row partial sums -> smem combine
            #pragma unroll
            for (int mi = 0; mi < 2; mi++) {
                #pragma unroll
                for (int hr = 0; hr < 2; hr++) {
                    float s = 0.f, s2 = 0.f;
                    #pragma unroll
                    for (int ni = 0; ni < 8; ni++) {
                        int col = nbase + ni * 8 + t * 2;
                        float x0 = acc[mi][ni][hr * 2]     + s_b2[col];
                        float x1 = acc[mi][ni][hr * 2 + 1] + s_b2[col + 1];
                        acc[mi][ni][hr * 2]     = x0;
                        acc[mi][ni][hr * 2 + 1] = x1;
                        s += x0 + x1;
                        s2 += x0 * x0 + x1 * x1;
                    }
                    s  += __shfl_xor_sync(0xffffffffu, s, 1);
                    s2 += __shfl_xor_sync(0xffffffffu, s2, 1);
                    s  += __shfl_xor_sync(0xffffffffu, s, 2);
                    s2 += __shfl_xor_sync(0xffffffffu, s2, 2);
                    if (t == 0) {
                        int r = mbase + mi * 16 + g + hr * 8;
                        s_red[r * 2 + (nbase >> 6)] = make_float2(s, s2);
                    }
                }
            }
            __syncthreads();

            // LayerNorm + coalesced-ish store straight from accumulators
            #pragma unroll
            for (int mi = 0; mi < 2; mi++) {
                #pragma unroll
                for (int hr = 0; hr < 2; hr++) {
                    int r = mbase + mi * 16 + g + hr * 8;
                    float2 p0 = s_red[r * 2], p1 = s_red[r * 2 + 1];
                    float ssum = p0.x + p1.x, ssq = p0.y + p1.y;
                    float mean = ssum * (1.f / 128.f);
                    float var  = ssq * (1.f / 128.f) - mean * mean;
                    float rstd = rsqrtf(var + 1e-5f);
                    int e = base + r;
                    if (e < E) {
                        float* po = out + (size_t)e * 128;
                        #pragma unroll
                        for (int ni = 0; ni < 8; ni++) {
                            int col = nbase + ni * 8 + t * 2;
                            float2 v;
                            v.x = (acc[mi][ni][hr * 2]     - mean) * rstd * s_g[col]     + s_bt[col];
                            v.y = (acc[mi][ni][hr * 2 + 1] - mean) * rstd * s_g[col + 1] + s_bt[col + 1];
                            *(float2*)(po + col) = v;
                        }
                    }
                }
            }
        }
    }
}

// ---------------------------------------------------------------------------
extern "C" void kernel_launch(void* const* d_in, const int* in_sizes, int n_in,
                              void* d_out, int out_size)
{
    const float* efeat   = (const float*)d_in[0];
    const float* nfeat   = (const float*)d_in[1];
    const int*   src_idx = (const int*)d_in[2];
    const int*   dst_idx = (const int*)d_in[3];
    const float* w_efeat = (const float*)d_in[4];
    const float* w_src   = (const float*)d_in[5];
    const float* w_dst   = (const float*)d_in[6];
    const float* b1      = (const float*)d_in[7];
    const float* w2      = (const float*)d_in[8];
    const float* b2      = (const float*)d_in[9];
    const float* ln_g    = (const float*)d_in[10];
    const float* ln_b    = (const float*)d_in[11];
    float* out = (float*)d_out;

    const int E = in_sizes[2];
    const int N = in_sizes[1] / 128;

    cudaFuncSetAttribute(fused_kernel, cudaFuncAttributeMaxDynamicSharedMemorySize, SMEM_SZ);

    int nsm = 148;
    cudaDeviceGetAttribute(&nsm, cudaDevAttrMultiProcessorCount, 0);

    fused_kernel<<<nsm, 256, SMEM_SZ>>>(efeat, nfeat, src_idx, dst_idx,
                                        w_efeat, w_src, w_dst, b1, w2, b2,
                                        ln_g, ln_b, out, E, N);
}

// round 11
// speedup vs baseline: 1.6373x; 1.1963x over previous
#include <cuda_runtime.h>
#include <cuda_fp16.h>
#include <cstdint>

// ===========================================================================
// MeshGraphEdgeMLPSum — single persistent kernel, 3 phases w/ grid barriers:
//   P0: split all 4 weight matrices into fp16 hi/lo (staged in gmem)
//   P1: node projections  P[n] = [nfeat@Ws^T | nfeat@Wd^T + b1]
//   P2: edge pipeline      out = LN( silu(ef@We^T + Ps[src]+Pd[dst]) @ W2^T + b2 )
// fp16 2-term GEMMs (act rounded once, W = Wh + Wl), fp32 accumulate,
// mma.sync.m16n8k16.f16 + ldmatrix.x4.
// 512 threads (16 warps, 4/SMSP), warp tile 32x32 -> 2x latency hiding vs R6.
// ===========================================================================

#define LDW 136   // padded fp16 row stride (272 B): ldmatrix conflict-free
#define NT  512   // threads per CTA

// ------------------------- globals ----------------------------------------
__device__ __half g_W[8][128 * LDW];   // We_h,We_l,W2_h,W2_l,Ws_h,Ws_l,Wd_h,Wd_l
__device__ float  g_P[50048 * 256];    // [node][0:128]=src proj, [128:256]=dst+b1
__device__ unsigned int g_cnt = 0;     // monotone grid-barrier counter

// ------------------------- smem layout ------------------------------------
#define SM_W     0                       // 4 x 128*LDW fp16 = 139264
#define SM_ACT   139264                  // 128*LDW fp16     =  34816
#define SM_RED   174080                  // float2[128*4]    =   4096
#define SM_IDXS  178176                  // int[128]
#define SM_IDXD  178688
#define SM_B2    179200
#define SM_G     179712
#define SM_BT    180224
#define SM_B1    180736
#define SMEM_SZ  181248

// ------------------------- helpers ----------------------------------------
__device__ __forceinline__ uint32_t smem_u32(const void* p) {
    uint32_t a;
    asm("{ .reg .u64 t; cvta.to.shared.u64 t, %1; cvt.u32.u64 %0, t; }" : "=r"(a) : "l"(p));
    return a;
}

__device__ __forceinline__ void ldsm4(uint32_t* r, uint32_t addr) {
    asm volatile("ldmatrix.sync.aligned.m8n8.x4.shared.b16 {%0,%1,%2,%3}, [%4];"
        : "=r"(r[0]), "=r"(r[1]), "=r"(r[2]), "=r"(r[3]) : "r"(addr));
}

__device__ __forceinline__ void mma_f16(float* c, const uint32_t* a, uint32_t b0, uint32_t b1) {
    asm volatile(
        "mma.sync.aligned.m16n8k16.row.col.f32.f16.f16.f32 "
        "{%0,%1,%2,%3}, {%4,%5,%6,%7}, {%8,%9}, {%0,%1,%2,%3};\n"
        : "+f"(c[0]), "+f"(c[1]), "+f"(c[2]), "+f"(c[3])
        : "r"(a[0]), "r"(a[1]), "r"(a[2]), "r"(a[3]), "r"(b0), "r"(b1));
}

// monotone grid barrier: no reset needed across graph replays
__device__ __forceinline__ void grid_barrier(int nctas) {
    __syncthreads();
    if (threadIdx.x == 0) {
        __threadfence();
        unsigned int t = atomicAdd(&g_cnt, 1u) + 1u;
        unsigned int target = ((t + (unsigned)nctas - 1u) / (unsigned)nctas) * (unsigned)nctas;
        unsigned int cur;
        do {
            asm volatile("ld.acquire.gpu.u32 %0, [%1];" : "=r"(cur) : "l"(&g_cnt));
        } while (cur < target);
    }
    __syncthreads();
}

// acc += A @ (Wh + Wl)^T : fp16 2-term, ldmatrix.x4 fragments.
// 16 warps, warp grid 4(M)x4(N), warp tile 32x32, acc[2][4][4].
__device__ __forceinline__ void gemm2(
    const __half* A, const __half* Wh, const __half* Wl,
    float acc[2][4][4], int mbase, int nbase, int lane)
{
    const int rowA = lane & 15;
    const int colA = (lane >> 4) << 3;
    uint32_t aA = smem_u32(A) + (uint32_t)(((mbase + rowA) * LDW + colA) * 2);
    const int rowB = (lane & 7) + ((lane & 16) >> 1);
    const int colB = lane & 8;
    uint32_t aBh = smem_u32(Wh) + (uint32_t)(((nbase + rowB) * LDW + colB) * 2);
    uint32_t aBl = smem_u32(Wl) + (uint32_t)(((nbase + rowB) * LDW + colB) * 2);
    const uint32_t MI = 16 * LDW * 2;

    #pragma unroll
    for (int k0 = 0; k0 < 128; k0 += 16) {
        uint32_t a0[4], a1[4], bh[2][4], bl[2][4];
        ldsm4(a0, aA + k0 * 2);
        ldsm4(a1, aA + MI + k0 * 2);
        #pragma unroll
        for (int p = 0; p < 2; p++) {
            ldsm4(bh[p], aBh + p * MI + k0 * 2);
            ldsm4(bl[p], aBl + p * MI + k0 * 2);
        }
        #pragma unroll
        for (int ni = 0; ni < 4; ni++) {
            mma_f16(acc[0][ni], a0, bh[ni >> 1][(ni & 1) * 2], bh[ni >> 1][(ni & 1) * 2 + 1]);
            mma_f16(acc[1][ni], a1, bh[ni >> 1][(ni & 1) * 2], bh[ni >> 1][(ni & 1) * 2 + 1]);
        }
        #pragma unroll
        for (int ni = 0; ni < 4; ni++) {
            mma_f16(acc[0][ni], a0, bl[ni >> 1][(ni & 1) * 2], bl[ni >> 1][(ni & 1) * 2 + 1]);
            mma_f16(acc[1][ni], a1, bl[ni >> 1][(ni & 1) * 2], bl[ni >> 1][(ni & 1) * 2 + 1]);
        }
    }
}

__device__ __forceinline__ void zero_acc(float acc[2][4][4]) {
    #pragma unroll
    for (int mi = 0; mi < 2; mi++)
        #pragma unroll
        for (int ni = 0; ni < 4; ni++)
            #pragma unroll
            for (int j = 0; j < 4; j++)
                acc[mi][ni][j] = 0.f;
}

// ------------------------- the fused persistent kernel --------------------
__global__ __launch_bounds__(NT, 1)
void fused_kernel(const float* __restrict__ efeat, const float* __restrict__ nfeat,
                  const int* __restrict__ src_idx, const int* __restrict__ dst_idx,
                  const float* __restrict__ w_efeat, const float* __restrict__ w_src,
                  const float* __restrict__ w_dst,  const float* __restrict__ b1,
                  const float* __restrict__ w2,     const float* __restrict__ b2,
                  const float* __restrict__ ln_g,   const float* __restrict__ ln_b,
                  float* __restrict__ out, int E, int Nn)
{
    extern __shared__ char sm[];
    __half* Wsm   = (__half*)(sm + SM_W);
    __half* Act   = (__half*)(sm + SM_ACT);
    float2* s_red = (float2*)(sm + SM_RED);       // [row*4 + nquad]
    int*    s_src = (int*)(sm + SM_IDXS);
    int*    s_dst = (int*)(sm + SM_IDXD);
    float*  s_b2  = (float*)(sm + SM_B2);
    float*  s_g   = (float*)(sm + SM_G);
    float*  s_bt  = (float*)(sm + SM_BT);
    float*  s_b1  = (float*)(sm + SM_B1);

    const int tid = threadIdx.x;
    const int nctas = gridDim.x;
    const int warp = tid >> 5, lane = tid & 31, g = lane >> 2, t = lane & 3;
    const int mbase = (warp >> 2) * 32, nbase = (warp & 3) * 32;

    // ---------------- phase 0: weight split (fp16 hi/lo) ----------------
    {
        const float* srcs[4] = { w_efeat, w2, w_src, w_dst };
        for (int i = blockIdx.x * NT + tid; i < 4 * 16384; i += nctas * NT) {
            int mat = i >> 14, idx = i & 16383;
            int r = idx >> 7, c = idx & 127;
            float v = srcs[mat][r * 128 + c];
            __half h = __float2half(v);
            __half l = __float2half(v - __half2float(h));
            g_W[2 * mat][r * LDW + c]     = h;
            g_W[2 * mat + 1][r * LDW + c] = l;
        }
    }
    grid_barrier(nctas);

    // ---------------- phase 1: node projections -------------------------
    {
        const uint4* s = (const uint4*)g_W[4];
        uint4* d = (uint4*)Wsm;
        for (int i = tid; i < 4 * 128 * LDW * 2 / 16; i += NT) d[i] = s[i];
        if (tid < 128) s_b1[tid] = b1[tid];
        __syncthreads();

        const int ntile = (Nn + 127) >> 7;
        for (int tile = blockIdx.x; tile < ntile; tile += nctas) {
            const int base = tile << 7;
            __syncthreads();  // prev tile's gemm reads of Act done

            #pragma unroll 2
            for (int i = tid; i < 128 * 32; i += NT) {
                int r = i >> 5, c4 = (i & 31) * 4;
                int node = base + r;
                float4 v = make_float4(0.f, 0.f, 0.f, 0.f);
                if (node < Nn) v = *(const float4*)(nfeat + (size_t)node * 128 + c4);
                *(__half2*)(Act + r * LDW + c4)     = __floats2half2_rn(v.x, v.y);
                *(__half2*)(Act + r * LDW + c4 + 2) = __floats2half2_rn(v.z, v.w);
            }
            __syncthreads();

            #pragma unroll
            for (int half = 0; half < 2; half++) {
                float acc[2][4][4];
                zero_acc(acc);
                gemm2(Act, Wsm + (half * 2) * 128 * LDW, Wsm + (half * 2 + 1) * 128 * LDW,
                      acc, mbase, nbase, lane);
                #pragma unroll
                for (int mi = 0; mi < 2; mi++) {
                    int r0 = mbase + mi * 16 + g;
                    int n0 = base + r0, n1 = n0 + 8;
                    #pragma unroll
                    for (int ni = 0; ni < 4; ni++) {
                        int col = nbase + ni * 8 + t * 2;
                        float bx = half ? s_b1[col]     : 0.f;
                        float by = half ? s_b1[col + 1] : 0.f;
                        if (n0 < Nn) {
                            float2 v = {acc[mi][ni][0] + bx, acc[mi][ni][1] + by};
                            *(float2*)(g_P + (size_t)n0 * 256 + half * 128 + col) = v;
                        }
                        if (n1 < Nn) {
                            float2 v = {acc[mi][ni][2] + bx, acc[mi][ni][3] + by};
                            *(float2*)(g_P + (size_t)n1 * 256 + half * 128 + col) = v;
                        }
                    }
                }
            }
        }
    }
    grid_barrier(nctas);

    // ---------------- phase 2: edge pipeline ----------------------------
    {
        const uint4* s = (const uint4*)g_W[0];
        uint4* d = (uint4*)Wsm;
        for (int i = tid; i < 4 * 128 * LDW * 2 / 16; i += NT) d[i] = s[i];
        if (tid < 128) { s_b2[tid] = b2[tid]; s_g[tid] = ln_g[tid]; s_bt[tid] = ln_b[tid]; }

        const int ntiles = (E + 127) >> 7;
        for (int tile = blockIdx.x; tile < ntiles; tile += nctas) {
            const int base = tile << 7;
            __syncthreads();  // prev tile fully consumed

            if (tid < 128) {
                int e = base + tid;
                s_src[tid] = (e < E) ? src_idx[e] : 0;
                s_dst[tid] = (e < E) ? dst_idx[e] : 0;
            }
            #pragma unroll 2
            for (int i = tid; i < 128 * 32; i += NT) {
                int r = i >> 5, c4 = (i & 31) * 4;
                int e = base + r;
                float4 v = make_float4(0.f, 0.f, 0.f, 0.f);
                if (e < E) v = *(const float4*)(efeat + (size_t)e * 128 + c4);
                *(__half2*)(Act + r * LDW + c4)     = __floats2half2_rn(v.x, v.y);
                *(__half2*)(Act + r * LDW + c4 + 2) = __floats2half2_rn(v.z, v.w);
            }
            __syncthreads();

            // GEMM1: efeat @ We^T
            float acc[2][4][4];
            zero_acc(acc);
            gemm2(Act, Wsm, Wsm + 128 * LDW, acc, mbase, nbase, lane);

            // gather node projections + SiLU, folded into acc (regs only)
            #pragma unroll
            for (int mi = 0; mi < 2; mi++) {
                int r0 = mbase + mi * 16 + g, r1 = r0 + 8;
                const float* Ps0 = g_P + (size_t)s_src[r0] * 256;
                const float* Pd0 = g_P + (size_t)s_dst[r0] * 256 + 128;
                const float* Ps1 = g_P + (size_t)s_src[r1] * 256;
                const float* Pd1 = g_P + (size_t)s_dst[r1] * 256 + 128;
                #pragma unroll
                for (int ni = 0; ni < 4; ni++) {
                    int col = nbase + ni * 8 + t * 2;
                    float2 a = *(const float2*)(Ps0 + col);
                    float2 b = *(const float2*)(Pd0 + col);
                    float2 c = *(const float2*)(Ps1 + col);
                    float2 dd = *(const float2*)(Pd1 + col);
                    float x0 = acc[mi][ni][0] + a.x + b.x;
                    float x1 = acc[mi][ni][1] + a.y + b.y;
                    float x2 = acc[mi][ni][2] + c.x + dd.x;
                    float x3 = acc[mi][ni][3] + c.y + dd.y;
                    acc[mi][ni][0] = x0 / (1.f + __expf(-x0));
                    acc[mi][ni][1] = x1 / (1.f + __expf(-x1));
                    acc[mi][ni][2] = x2 / (1.f + __expf(-x2));
                    acc[mi][ni][3] = x3 / (1.f + __expf(-x3));
                }
            }
            __syncthreads();  // all warps done reading Act (GEMM1)

            // hidden -> Act (single fp16 tile)
            #pragma unroll
            for (int mi = 0; mi < 2; mi++) {
                int r0 = mbase + mi * 16 + g, r1 = r0 + 8;
                #pragma unroll
                for (int ni = 0; ni < 4; ni++) {
                    int col = nbase + ni * 8 + t * 2;
                    *(__half2*)(Act + r0 * LDW + col) =
                        __floats2half2_rn(acc[mi][ni][0], acc[mi][ni][1]);
                    *(__half2*)(Act + r1 * LDW + col) =
                        __floats2half2_rn(acc[mi][ni][2], acc[mi][ni][3]);
                }
            }
            __syncthreads();

            // GEMM2: hidden @ W2^T
            zero_acc(acc);
            gemm2(Act, Wsm + 2 * 128 * LDW, Wsm + 3 * 128 * LDW, acc, mbase, nbase, lane);

            // +b2, per-row partial sums -> smem combine
            #pragma unroll
            for (int mi = 0; mi < 2; mi++) {
                #pragma unroll
                for (int hr = 0; hr < 2; hr++) {
                    float s = 0.f, s2 = 0.f;
                    #pragma unroll
                    for (int ni = 0; ni < 4; ni++) {
                        int col = nbase + ni * 8 + t * 2;
                        float x0 = acc[mi][ni][hr * 2]     + s_b2[col];
                        float x1 = acc[mi][ni][hr * 2 + 1] + s_b2[col + 1];
                        acc[mi][ni][hr * 2]     = x0;
                        acc[mi][ni][hr * 2 + 1] = x1;
                        s += x0 + x1;
                        s2 += x0 * x0 + x1 * x1;
                    }
                    s  += __shfl_xor_sync(0xffffffffu, s, 1);
                    s2 += __shfl_xor_sync(0xffffffffu, s2, 1);
                    s  += __shfl_xor_sync(0xffffffffu, s, 2);
                    s2 += __shfl_xor_sync(0xffffffffu, s2, 2);
                    if (t == 0) {
                        int r = mbase + mi * 16 + g + hr * 8;
                        s_red[r * 4 + (nbase >> 5)] = make_float2(s, s2);
                    }
                }
            }
            __syncthreads();

            // LayerNorm + store straight from accumulators
            #pragma unroll
            for (int mi = 0; mi < 2; mi++) {
                #pragma unroll
                for (int hr = 0; hr < 2; hr++) {
                    int r = mbase + mi * 16 + g + hr * 8;
                    float2 p0 = s_red[r * 4], p1 = s_red[r * 4 + 1];
                    float2 p2 = s_red[r * 4 + 2], p3 = s_red[r * 4 + 3];
                    float ssum = (p0.x + p1.x) + (p2.x + p3.x);
                    float ssq  = (p0.y + p1.y) + (p2.y + p3.y);
                    float mean = ssum * (1.f / 128.f);
                    float var  = ssq * (1.f / 128.f) - mean * mean;
                    float rstd = rsqrtf(var + 1e-5f);
                    int e = base + r;
                    if (e < E) {
                        float* po = out + (size_t)e * 128;
                        #pragma unroll
                        for (int ni = 0; ni < 4; ni++) {
                            int col = nbase + ni * 8 + t * 2;
                            float2 v;
                            v.x = (acc[mi][ni][hr * 2]     - mean) * rstd * s_g[col]     + s_bt[col];
                            v.y = (acc[mi][ni][hr * 2 + 1] - mean) * rstd * s_g[col + 1] + s_bt[col + 1];
                            *(float2*)(po + col) = v;
                        }
                    }
                }
            }
        }
    }
}

// ---------------------------------------------------------------------------
extern "C" void kernel_launch(void* const* d_in, const int* in_sizes, int n_in,
                              void* d_out, int out_size)
{
    const float* efeat   = (const float*)d_in[0];
    const float* nfeat   = (const float*)d_in[1];
    const int*   src_idx = (const int*)d_in[2];
    const int*   dst_idx = (const int*)d_in[3];
    const float* w_efeat = (const float*)d_in[4];
    const float* w_src   = (const float*)d_in[5];
    const float* w_dst   = (const float*)d_in[6];
    const float* b1      = (const float*)d_in[7];
    const float* w2      = (const float*)d_in[8];
    const float* b2      = (const float*)d_in[9];
    const float* ln_g    = (const float*)d_in[10];
    const float* ln_b    = (const float*)d_in[11];
    float* out = (float*)d_out;

    const int E = in_sizes[2];
    const int N = in_sizes[1] / 128;

    cudaFuncSetAttribute(fused_kernel, cudaFuncAttributeMaxDynamicSharedMemorySize, SMEM_SZ);

    // 1 CTA/SM persistent grid. Fallback 148 (fewer CTAs than SMs is safe for
    // the grid barrier; more would deadlock).
    int nsm = 148;
    if (cudaDeviceGetAttribute(&nsm, cudaDevAttrMultiProcessorCount, 0) != cudaSuccess || nsm <= 0)
        nsm = 148;

    fused_kernel<<<nsm, NT, SMEM_SZ>>>(efeat, nfeat, src_idx, dst_idx,
                                       w_efeat, w_src, w_dst, b1, w2, b2,
                                       ln_g, ln_b, out, E, N);
}

// round 12
// speedup vs baseline: 1.9359x; 1.1824x over previous
#include <cuda_runtime.h>
#include <cuda_fp16.h>
#include <cstdint>

// ===========================================================================
// MeshGraphEdgeMLPSum — single persistent kernel, 3 phases w/ grid barriers:
//   P0: round all 4 weight matrices to fp16 (staged in gmem, padded stride)
//   P1: node projections  P[n] = fp16[ nfeat@Ws^T | nfeat@Wd^T + b1 ]
//   P2: edge pipeline      out = LN( silu(ef@We^T + Ps[src]+Pd[dst]) @ W2^T + b2 )
// fp16 1-term GEMMs, fp32 accumulate, mma.sync.m16n8k16.f16 + ldmatrix.x4.
// P gathers prefetched into smem via cp.async, waited AFTER GEMM1's MMAs so
// the L2 gather latency hides behind tensor work.
// 512 threads (16 warps, 4/SMSP), warp tile 32x32.
// ===========================================================================

#define LDW 136   // padded fp16 row stride (272 B): ldmatrix/LDS conflict-free
#define NT  512   // threads per CTA
#define MATB (128 * LDW * 2)   // 34816 B per fp16 matrix

// ------------------------- globals ----------------------------------------
__device__ __half g_W[4][128 * LDW];   // We, W2, Ws, Wd (fp16, padded)
__device__ __half g_P[50048 * 256];    // [node][0:128]=src proj, [128:256]=dst+b1
__device__ unsigned int g_cnt = 0;     // monotone grid-barrier counter

// ------------------------- smem layout ------------------------------------
#define SM_W     0                       // 2 matrices (per phase) = 69632
#define SM_ACT   69632                   // 34816
#define SM_PS    104448                  // gather stage src, 128 x LDW fp16
#define SM_PD    139264                  // gather stage dst
#define SM_RED   174080                  // float2[128*4] = 4096
#define SM_B2    178176
#define SM_G     178688
#define SM_BT    179200
#define SM_B1    179712
#define SMEM_SZ  180224

// ------------------------- helpers ----------------------------------------
__device__ __forceinline__ uint32_t smem_u32(const void* p) {
    uint32_t a;
    asm("{ .reg .u64 t; cvta.to.shared.u64 t, %1; cvt.u32.u64 %0, t; }" : "=r"(a) : "l"(p));
    return a;
}

__device__ __forceinline__ void ldsm4(uint32_t* r, uint32_t addr) {
    asm volatile("ldmatrix.sync.aligned.m8n8.x4.shared.b16 {%0,%1,%2,%3}, [%4];"
        : "=r"(r[0]), "=r"(r[1]), "=r"(r[2]), "=r"(r[3]) : "r"(addr));
}

__device__ __forceinline__ void mma_f16(float* c, const uint32_t* a, uint32_t b0, uint32_t b1) {
    asm volatile(
        "mma.sync.aligned.m16n8k16.row.col.f32.f16.f16.f32 "
        "{%0,%1,%2,%3}, {%4,%5,%6,%7}, {%8,%9}, {%0,%1,%2,%3};\n"
        : "+f"(c[0]), "+f"(c[1]), "+f"(c[2]), "+f"(c[3])
        : "r"(a[0]), "r"(a[1]), "r"(a[2]), "r"(a[3]), "r"(b0), "r"(b1));
}

__device__ __forceinline__ void cp16(uint32_t dst, const void* src) {
    asm volatile("cp.async.cg.shared.global [%0], [%1], 16;" :: "r"(dst), "l"(src));
}
#define CP_COMMIT() asm volatile("cp.async.commit_group;" ::: "memory")
#define CP_WAIT0()  asm volatile("cp.async.wait_group 0;" ::: "memory")

// monotone grid barrier: no reset needed across graph replays
__device__ __forceinline__ void grid_barrier(int nctas) {
    __syncthreads();
    if (threadIdx.x == 0) {
        __threadfence();
        unsigned int t = atomicAdd(&g_cnt, 1u) + 1u;
        unsigned int target = ((t + (unsigned)nctas - 1u) / (unsigned)nctas) * (unsigned)nctas;
        unsigned int cur;
        do {
            asm volatile("ld.acquire.gpu.u32 %0, [%1];" : "=r"(cur) : "l"(&g_cnt));
        } while (cur < target);
    }
    __syncthreads();
}

// acc += A @ W^T : fp16 1-term, ldmatrix.x4 fragments.
// 16 warps, warp grid 4(M)x4(N), warp tile 32x32, acc[2][4][4].
__device__ __forceinline__ void gemm1(
    const __half* A, const __half* W,
    float acc[2][4][4], int mbase, int nbase, int lane)
{
    const int rowA = lane & 15;
    const int colA = (lane >> 4) << 3;
    uint32_t aA = smem_u32(A) + (uint32_t)(((mbase + rowA) * LDW + colA) * 2);
    const int rowB = (lane & 7) + ((lane & 16) >> 1);
    const int colB = lane & 8;
    uint32_t aB = smem_u32(W) + (uint32_t)(((nbase + rowB) * LDW + colB) * 2);
    const uint32_t MI = 16 * LDW * 2;

    #pragma unroll
    for (int k0 = 0; k0 < 128; k0 += 16) {
        uint32_t a0[4], a1[4], b[2][4];
        ldsm4(a0, aA + k0 * 2);
        ldsm4(a1, aA + MI + k0 * 2);
        ldsm4(b[0], aB + k0 * 2);
        ldsm4(b[1], aB + MI + k0 * 2);
        #pragma unroll
        for (int ni = 0; ni < 4; ni++) {
            mma_f16(acc[0][ni], a0, b[ni >> 1][(ni & 1) * 2], b[ni >> 1][(ni & 1) * 2 + 1]);
            mma_f16(acc[1][ni], a1, b[ni >> 1][(ni & 1) * 2], b[ni >> 1][(ni & 1) * 2 + 1]);
        }
    }
}

__device__ __forceinline__ void zero_acc(float acc[2][4][4]) {
    #pragma unroll
    for (int mi = 0; mi < 2; mi++)
        #pragma unroll
        for (int ni = 0; ni < 4; ni++)
            #pragma unroll
            for (int j = 0; j < 4; j++)
                acc[mi][ni][j] = 0.f;
}

// ------------------------- the fused persistent kernel --------------------
__global__ __launch_bounds__(NT, 1)
void fused_kernel(const float* __restrict__ efeat, const float* __restrict__ nfeat,
                  const int* __restrict__ src_idx, const int* __restrict__ dst_idx,
                  const float* __restrict__ w_efeat, const float* __restrict__ w_src,
                  const float* __restrict__ w_dst,  const float* __restrict__ b1,
                  const float* __restrict__ w2,     const float* __restrict__ b2,
                  const float* __restrict__ ln_g,   const float* __restrict__ ln_b,
                  float* __restrict__ out, int E, int Nn)
{
    extern __shared__ char sm[];
    __half* Wsm   = (__half*)(sm + SM_W);
    __half* Act   = (__half*)(sm + SM_ACT);
    __half* Ps_s  = (__half*)(sm + SM_PS);
    __half* Pd_s  = (__half*)(sm + SM_PD);
    float2* s_red = (float2*)(sm + SM_RED);
    float*  s_b2  = (float*)(sm + SM_B2);
    float*  s_g   = (float*)(sm + SM_G);
    float*  s_bt  = (float*)(sm + SM_BT);
    float*  s_b1  = (float*)(sm + SM_B1);

    const int tid = threadIdx.x;
    const int nctas = gridDim.x;
    const int warp = tid >> 5, lane = tid & 31, g = lane >> 2, t = lane & 3;
    const int mbase = (warp >> 2) * 32, nbase = (warp & 3) * 32;

    // ---------------- phase 0: weight rounding (fp16, padded) -----------
    {
        const float* srcs[4] = { w_efeat, w2, w_src, w_dst };
        for (int i = blockIdx.x * NT + tid; i < 4 * 16384; i += nctas * NT) {
            int mat = i >> 14, idx = i & 16383;
            int r = idx >> 7, c = idx & 127;
            g_W[mat][r * LDW + c] = __float2half(srcs[mat][r * 128 + c]);
        }
    }
    grid_barrier(nctas);

    // ---------------- phase 1: node projections -> fp16 P ---------------
    {
        const uint4* s = (const uint4*)g_W[2];   // Ws, Wd
        uint4* d = (uint4*)Wsm;
        for (int i = tid; i < 2 * MATB / 16; i += NT) d[i] = s[i];
        if (tid < 128) s_b1[tid] = b1[tid];
        __syncthreads();

        const int ntile = (Nn + 127) >> 7;
        for (int tile = blockIdx.x; tile < ntile; tile += nctas) {
            const int base = tile << 7;
            __syncthreads();  // prev tile's gemm reads of Act done

            #pragma unroll 2
            for (int i = tid; i < 128 * 32; i += NT) {
                int r = i >> 5, c4 = (i & 31) * 4;
                int node = base + r;
                float4 v = make_float4(0.f, 0.f, 0.f, 0.f);
                if (node < Nn) v = *(const float4*)(nfeat + (size_t)node * 128 + c4);
                *(__half2*)(Act + r * LDW + c4)     = __floats2half2_rn(v.x, v.y);
                *(__half2*)(Act + r * LDW + c4 + 2) = __floats2half2_rn(v.z, v.w);
            }
            __syncthreads();

            #pragma unroll
            for (int half = 0; half < 2; half++) {
                float acc[2][4][4];
                zero_acc(acc);
                gemm1(Act, Wsm + half * 128 * LDW, acc, mbase, nbase, lane);
                #pragma unroll
                for (int mi = 0; mi < 2; mi++) {
                    int r0 = mbase + mi * 16 + g;
                    int n0 = base + r0, n1 = n0 + 8;
                    #pragma unroll
                    for (int ni = 0; ni < 4; ni++) {
                        int col = nbase + ni * 8 + t * 2;
                        float bx = half ? s_b1[col]     : 0.f;
                        float by = half ? s_b1[col + 1] : 0.f;
                        if (n0 < Nn)
                            *(__half2*)(g_P + (size_t)n0 * 256 + half * 128 + col) =
                                __floats2half2_rn(acc[mi][ni][0] + bx, acc[mi][ni][1] + by);
                        if (n1 < Nn)
                            *(__half2*)(g_P + (size_t)n1 * 256 + half * 128 + col) =
                                __floats2half2_rn(acc[mi][ni][2] + bx, acc[mi][ni][3] + by);
                    }
                }
            }
        }
    }
    grid_barrier(nctas);

    // ---------------- phase 2: edge pipeline ----------------------------
    {
        const uint4* s = (const uint4*)g_W[0];   // We, W2
        uint4* d = (uint4*)Wsm;
        for (int i = tid; i < 2 * MATB / 16; i += NT) d[i] = s[i];
        if (tid < 128) { s_b2[tid] = b2[tid]; s_g[tid] = ln_g[tid]; s_bt[tid] = ln_b[tid]; }

        const uint32_t ps_base = smem_u32(Ps_s), pd_base = smem_u32(Pd_s);
        const int ntiles = (E + 127) >> 7;

        for (int tile = blockIdx.x; tile < ntiles; tile += nctas) {
            const int base = tile << 7;
            __syncthreads();  // prev tile fully consumed (Act, stages, s_red)

            // ---- issue P gathers via cp.async (completion awaited after GEMM1)
            {
                int r = (tid & 255) >> 1, hf = tid & 1;
                int e = base + r;
                if (tid < 256) {
                    int node = (e < E) ? src_idx[e] : 0;
                    const char* srcp = (const char*)g_P + (size_t)node * 512 + hf * 128;
                    uint32_t dstp = ps_base + (uint32_t)(r * 272 + hf * 128);
                    #pragma unroll
                    for (int j = 0; j < 8; j++) cp16(dstp + j * 16, srcp + j * 16);
                } else {
                    int node = (e < E) ? dst_idx[e] : 0;
                    const char* srcp = (const char*)g_P + (size_t)node * 512 + 256 + hf * 128;
                    uint32_t dstp = pd_base + (uint32_t)(r * 272 + hf * 128);
                    #pragma unroll
                    for (int j = 0; j < 8; j++) cp16(dstp + j * 16, srcp + j * 16);
                }
                CP_COMMIT();
            }

            // ---- efeat tile -> fp16 Act
            #pragma unroll 2
            for (int i = tid; i < 128 * 32; i += NT) {
                int r = i >> 5, c4 = (i & 31) * 4;
                int e = base + r;
                float4 v = make_float4(0.f, 0.f, 0.f, 0.f);
                if (e < E) v = *(const float4*)(efeat + (size_t)e * 128 + c4);
                *(__half2*)(Act + r * LDW + c4)     = __floats2half2_rn(v.x, v.y);
                *(__half2*)(Act + r * LDW + c4 + 2) = __floats2half2_rn(v.z, v.w);
            }
            __syncthreads();

            // ---- GEMM1: efeat @ We^T (gathers still in flight)
            float acc[2][4][4];
            zero_acc(acc);
            gemm1(Act, Wsm, acc, mbase, nbase, lane);

            CP_WAIT0();
            __syncthreads();  // all warps: GEMM1 done + all gathers visible

            // ---- epilogue 1: + Ps + Pd (LDS), SiLU, hidden -> Act
            #pragma unroll
            for (int mi = 0; mi < 2; mi++) {
                int r0 = mbase + mi * 16 + g, r1 = r0 + 8;
                #pragma unroll
                for (int ni = 0; ni < 4; ni++) {
                    int col = nbase + ni * 8 + t * 2;
                    float2 a = __half22float2(*(__half2*)(Ps_s + r0 * LDW + col));
                    float2 b = __half22float2(*(__half2*)(Pd_s + r0 * LDW + col));
                    float2 c = __half22float2(*(__half2*)(Ps_s + r1 * LDW + col));
                    float2 dd = __half22float2(*(__half2*)(Pd_s + r1 * LDW + col));
                    float x0 = acc[mi][ni][0] + a.x + b.x;
                    float x1 = acc[mi][ni][1] + a.y + b.y;
                    float x2 = acc[mi][ni][2] + c.x + dd.x;
                    float x3 = acc[mi][ni][3] + c.y + dd.y;
                    x0 = x0 / (1.f + __expf(-x0));
                    x1 = x1 / (1.f + __expf(-x1));
                    x2 = x2 / (1.f + __expf(-x2));
                    x3 = x3 / (1.f + __expf(-x3));
                    *(__half2*)(Act + r0 * LDW + col) = __floats2half2_rn(x0, x1);
                    *(__half2*)(Act + r1 * LDW + col) = __floats2half2_rn(x2, x3);
                }
            }
            __syncthreads();

            // ---- GEMM2: hidden @ W2^T
            zero_acc(acc);
            gemm1(Act, Wsm + 128 * LDW, acc, mbase, nbase, lane);

            // ---- +b2, per-row partial sums -> smem combine
            #pragma unroll
            for (int mi = 0; mi < 2; mi++) {
                #pragma unroll
                for (int hr = 0; hr < 2; hr++) {
                    float s = 0.f, s2 = 0.f;
                    #pragma unroll
                    for (int ni = 0; ni < 4; ni++) {
                        int col = nbase + ni * 8 + t * 2;
                        float x0 = acc[mi][ni][hr * 2]     + s_b2[col];
                        float x1 = acc[mi][ni][hr * 2 + 1] + s_b2[col + 1];
                        acc[mi][ni][hr * 2]     = x0;
                        acc[mi][ni][hr * 2 + 1] = x1;
                        s += x0 + x1;
                        s2 += x0 * x0 + x1 * x1;
                    }
                    s  += __shfl_xor_sync(0xffffffffu, s, 1);
                    s2 += __shfl_xor_sync(0xffffffffu, s2, 1);
                    s  += __shfl_xor_sync(0xffffffffu, s, 2);
                    s2 += __shfl_xor_sync(0xffffffffu, s2, 2);
                    if (t == 0) {
                        int r = mbase + mi * 16 + g + hr * 8;
                        s_red[r * 4 + (nbase >> 5)] = make_float2(s, s2);
                    }
                }
            }
            __syncthreads();

            // ---- LayerNorm + store straight from accumulators
            #pragma unroll
            for (int mi = 0; mi < 2; mi++) {
                #pragma unroll
                for (int hr = 0; hr < 2; hr++) {
                    int r = mbase + mi * 16 + g + hr * 8;
                    float2 p0 = s_red[r * 4], p1 = s_red[r * 4 + 1];
                    float2 p2 = s_red[r * 4 + 2], p3 = s_red[r * 4 + 3];
                    float ssum = (p0.x + p1.x) + (p2.x + p3.x);
                    float ssq  = (p0.y + p1.y) + (p2.y + p3.y);
                    float mean = ssum * (1.f / 128.f);
                    float var  = ssq * (1.f / 128.f) - mean * mean;
                    float rstd = rsqrtf(var + 1e-5f);
                    int e = base + r;
                    if (e < E) {
                        float* po = out + (size_t)e * 128;
                        #pragma unroll
                        for (int ni = 0; ni < 4; ni++) {
                            int col = nbase + ni * 8 + t * 2;
                            float2 v;
                            v.x = (acc[mi][ni][hr * 2]     - mean) * rstd * s_g[col]     + s_bt[col];
                            v.y = (acc[mi][ni][hr * 2 + 1] - mean) * rstd * s_g[col + 1] + s_bt[col + 1];
                            *(float2*)(po + col) = v;
                        }
                    }
                }
            }
        }
    }
}

// ---------------------------------------------------------------------------
extern "C" void kernel_launch(void* const* d_in, const int* in_sizes, int n_in,
                              void* d_out, int out_size)
{
    const float* efeat   = (const float*)d_in[0];
    const float* nfeat   = (const float*)d_in[1];
    const int*   src_idx = (const int*)d_in[2];
    const int*   dst_idx = (const int*)d_in[3];
    const float* w_efeat = (const float*)d_in[4];
    const float* w_src   = (const float*)d_in[5];
    const float* w_dst   = (const float*)d_in[6];
    const float* b1      = (const float*)d_in[7];
    const float* w2      = (const float*)d_in[8];
    const float* b2      = (const float*)d_in[9];
    const float* ln_g    = (const float*)d_in[10];
    const float* ln_b    = (const float*)d_in[11];
    float* out = (float*)d_out;

    const int E = in_sizes[2];
    const int N = in_sizes[1] / 128;

    cudaFuncSetAttribute(fused_kernel, cudaFuncAttributeMaxDynamicSharedMemorySize, SMEM_SZ);

    // 1 CTA/SM persistent grid; fewer CTAs than SMs stays safe for the barrier.
    int nsm = 148;
    if (cudaDeviceGetAttribute(&nsm, cudaDevAttrMultiProcessorCount, 0) != cudaSuccess || nsm <= 0)
        nsm = 148;

    fused_kernel<<<nsm, NT, SMEM_SZ>>>(efeat, nfeat, src_idx, dst_idx,
                                       w_efeat, w_src, w_dst, b1, w2, b2,
                                       ln_g, ln_b, out, E, N);
}

// round 13
// speedup vs baseline: 1.9496x; 1.0071x over previous
#include <cuda_runtime.h>
#include <cuda_fp16.h>
#include <cstdint>

// ===========================================================================
// MeshGraphEdgeMLPSum — single persistent kernel, 3 phases w/ grid barriers:
//   P0: round all 4 weight matrices to fp16 (staged in gmem, padded stride)
//   P1: node projections  P[n] = fp16[ nfeat@Ws^T | nfeat@Wd^T + b1 ]
//   P2: edge pipeline      out = LN( silu(ef@We^T + Ps[src]+Pd[dst]) @ W2^T + b2 )
// fp16 1-term GEMMs, fp32 accumulate, mma.sync.m16n8k16.f16 + ldmatrix.x4.
// P gathers prefetched into smem via cp.async, waited AFTER GEMM1's MMAs.
// R13: phase 2 runs as TWO independent 256-thread groups (named barriers),
// each on its own 64-row tile -> groups interleave, hiding phase latency.
// ===========================================================================

#define LDW 136   // padded fp16 row stride (272 B): ldmatrix/LDS conflict-free
#define NT  512   // threads per CTA
#define MATB (128 * LDW * 2)   // 34816 B per fp16 matrix

// ------------------------- globals ----------------------------------------
__device__ __half g_W[4][128 * LDW];   // We, W2, Ws, Wd (fp16, padded)
__device__ __half g_P[50048 * 256];    // [node][0:128]=src proj, [128:256]=dst+b1
__device__ unsigned int g_cnt = 0;     // monotone grid-barrier counter

// ------------------------- smem layout ------------------------------------
#define SM_W     0                       // 2 matrices (per phase) = 69632
#define SM_ACT   69632                   // 34816 (group g uses rows [64g,64g+64))
#define SM_PS    104448                  // gather stage src
#define SM_PD    139264                  // gather stage dst
#define SM_RED   174080                  // float2[128*4] = 4096
#define SM_B2    178176
#define SM_G     178688
#define SM_BT    179200
#define SM_B1    179712
#define SMEM_SZ  180224

// ------------------------- helpers ----------------------------------------
__device__ __forceinline__ uint32_t smem_u32(const void* p) {
    uint32_t a;
    asm("{ .reg .u64 t; cvta.to.shared.u64 t, %1; cvt.u32.u64 %0, t; }" : "=r"(a) : "l"(p));
    return a;
}

__device__ __forceinline__ void ldsm4(uint32_t* r, uint32_t addr) {
    asm volatile("ldmatrix.sync.aligned.m8n8.x4.shared.b16 {%0,%1,%2,%3}, [%4];"
        : "=r"(r[0]), "=r"(r[1]), "=r"(r[2]), "=r"(r[3]) : "r"(addr));
}

__device__ __forceinline__ void mma_f16(float* c, const uint32_t* a, uint32_t b0, uint32_t b1) {
    asm volatile(
        "mma.sync.aligned.m16n8k16.row.col.f32.f16.f16.f32 "
        "{%0,%1,%2,%3}, {%4,%5,%6,%7}, {%8,%9}, {%0,%1,%2,%3};\n"
        : "+f"(c[0]), "+f"(c[1]), "+f"(c[2]), "+f"(c[3])
        : "r"(a[0]), "r"(a[1]), "r"(a[2]), "r"(a[3]), "r"(b0), "r"(b1));
}

__device__ __forceinline__ void cp16(uint32_t dst, const void* src) {
    asm volatile("cp.async.cg.shared.global [%0], [%1], 16;" :: "r"(dst), "l"(src));
}
#define CP_COMMIT() asm volatile("cp.async.commit_group;" ::: "memory")
#define CP_WAIT0()  asm volatile("cp.async.wait_group 0;" ::: "memory")

// group barrier: named barrier (id = group+1), 256 threads
__device__ __forceinline__ void gbar(int group) {
    asm volatile("bar.sync %0, 256;" :: "r"(group + 1) : "memory");
}

// monotone grid barrier: no reset needed across graph replays
__device__ __forceinline__ void grid_barrier(int nctas) {
    __syncthreads();
    if (threadIdx.x == 0) {
        __threadfence();
        unsigned int t = atomicAdd(&g_cnt, 1u) + 1u;
        unsigned int target = ((t + (unsigned)nctas - 1u) / (unsigned)nctas) * (unsigned)nctas;
        unsigned int cur;
        do {
            asm volatile("ld.acquire.gpu.u32 %0, [%1];" : "=r"(cur) : "l"(&g_cnt));
        } while (cur < target);
    }
    __syncthreads();
}

// acc += A @ W^T : fp16 1-term, ldmatrix.x4 fragments. Warp tile 32x32.
__device__ __forceinline__ void gemm1(
    const __half* A, const __half* W,
    float acc[2][4][4], int mbase, int nbase, int lane)
{
    const int rowA = lane & 15;
    const int colA = (lane >> 4) << 3;
    uint32_t aA = smem_u32(A) + (uint32_t)(((mbase + rowA) * LDW + colA) * 2);
    const int rowB = (lane & 7) + ((lane & 16) >> 1);
    const int colB = lane & 8;
    uint32_t aB = smem_u32(W) + (uint32_t)(((nbase + rowB) * LDW + colB) * 2);
    const uint32_t MI = 16 * LDW * 2;

    #pragma unroll
    for (int k0 = 0; k0 < 128; k0 += 16) {
        uint32_t a0[4], a1[4], b[2][4];
        ldsm4(a0, aA + k0 * 2);
        ldsm4(a1, aA + MI + k0 * 2);
        ldsm4(b[0], aB + k0 * 2);
        ldsm4(b[1], aB + MI + k0 * 2);
        #pragma unroll
        for (int ni = 0; ni < 4; ni++) {
            mma_f16(acc[0][ni], a0, b[ni >> 1][(ni & 1) * 2], b[ni >> 1][(ni & 1) * 2 + 1]);
            mma_f16(acc[1][ni], a1, b[ni >> 1][(ni & 1) * 2], b[ni >> 1][(ni & 1) * 2 + 1]);
        }
    }
}

__device__ __forceinline__ void zero_acc(float acc[2][4][4]) {
    #pragma unroll
    for (int mi = 0; mi < 2; mi++)
        #pragma unroll
        for (int ni = 0; ni < 4; ni++)
            #pragma unroll
            for (int j = 0; j < 4; j++)
                acc[mi][ni][j] = 0.f;
}

// ------------------------- the fused persistent kernel --------------------
__global__ __launch_bounds__(NT, 1)
void fused_kernel(const float* __restrict__ efeat, const float* __restrict__ nfeat,
                  const int* __restrict__ src_idx, const int* __restrict__ dst_idx,
                  const float* __restrict__ w_efeat, const float* __restrict__ w_src,
                  const float* __restrict__ w_dst,  const float* __restrict__ b1,
                  const float* __restrict__ w2,     const float* __restrict__ b2,
                  const float* __restrict__ ln_g,   const float* __restrict__ ln_b,
                  float* __restrict__ out, int E, int Nn)
{
    extern __shared__ char sm[];
    __half* Wsm   = (__half*)(sm + SM_W);
    __half* Act   = (__half*)(sm + SM_ACT);
    __half* Ps_s  = (__half*)(sm + SM_PS);
    __half* Pd_s  = (__half*)(sm + SM_PD);
    float2* s_red = (float2*)(sm + SM_RED);
    float*  s_b2  = (float*)(sm + SM_B2);
    float*  s_g   = (float*)(sm + SM_G);
    float*  s_bt  = (float*)(sm + SM_BT);
    float*  s_b1  = (float*)(sm + SM_B1);

    const int tid = threadIdx.x;
    const int nctas = gridDim.x;
    const int warp = tid >> 5, lane = tid & 31, g = lane >> 2, t = lane & 3;

    // ---------------- phase 0: weight rounding (fp16, padded) -----------
    {
        const float* srcs[4] = { w_efeat, w2, w_src, w_dst };
        for (int i = blockIdx.x * NT + tid; i < 4 * 16384; i += nctas * NT) {
            int mat = i >> 14, idx = i & 16383;
            int r = idx >> 7, c = idx & 127;
            g_W[mat][r * LDW + c] = __float2half(srcs[mat][r * 128 + c]);
        }
    }
    grid_barrier(nctas);

    // ---------------- phase 1: node projections -> fp16 P ---------------
    {
        const int mbase = (warp >> 2) * 32, nbase = (warp & 3) * 32;
        const uint4* s = (const uint4*)g_W[2];   // Ws, Wd
        uint4* d = (uint4*)Wsm;
        for (int i = tid; i < 2 * MATB / 16; i += NT) d[i] = s[i];
        if (tid < 128) s_b1[tid] = b1[tid];
        __syncthreads();

        const int ntile = (Nn + 127) >> 7;
        for (int tile = blockIdx.x; tile < ntile; tile += nctas) {
            const int base = tile << 7;
            __syncthreads();  // prev tile's gemm reads of Act done

            #pragma unroll 2
            for (int i = tid; i < 128 * 32; i += NT) {
                int r = i >> 5, c4 = (i & 31) * 4;
                int node = base + r;
                float4 v = make_float4(0.f, 0.f, 0.f, 0.f);
                if (node < Nn) v = *(const float4*)(nfeat + (size_t)node * 128 + c4);
                *(__half2*)(Act + r * LDW + c4)     = __floats2half2_rn(v.x, v.y);
                *(__half2*)(Act + r * LDW + c4 + 2) = __floats2half2_rn(v.z, v.w);
            }
            __syncthreads();

            #pragma unroll
            for (int half = 0; half < 2; half++) {
                float acc[2][4][4];
                zero_acc(acc);
                gemm1(Act, Wsm + half * 128 * LDW, acc, mbase, nbase, lane);
                #pragma unroll
                for (int mi = 0; mi < 2; mi++) {
                    int r0 = mbase + mi * 16 + g;
                    int n0 = base + r0, n1 = n0 + 8;
                    #pragma unroll
                    for (int ni = 0; ni < 4; ni++) {
                        int col = nbase + ni * 8 + t * 2;
                        float bx = half ? s_b1[col]     : 0.f;
                        float by = half ? s_b1[col + 1] : 0.f;
                        if (n0 < Nn)
                            *(__half2*)(g_P + (size_t)n0 * 256 + half * 128 + col) =
                                __floats2half2_rn(acc[mi][ni][0] + bx, acc[mi][ni][1] + by);
                        if (n1 < Nn)
                            *(__half2*)(g_P + (size_t)n1 * 256 + half * 128 + col) =
                                __floats2half2_rn(acc[mi][ni][2] + bx, acc[mi][ni][3] + by);
                    }
                }
            }
        }
    }
    grid_barrier(nctas);

    // ---------------- phase 2: edge pipeline, two independent groups ----
    {
        const uint4* s = (const uint4*)g_W[0];   // We, W2
        uint4* d = (uint4*)Wsm;
        for (int i = tid; i < 2 * MATB / 16; i += NT) d[i] = s[i];
        if (tid < 128) { s_b2[tid] = b2[tid]; s_g[tid] = ln_g[tid]; s_bt[tid] = ln_b[tid]; }
        __syncthreads();   // weights + consts visible to both groups

        const int group = tid >> 8;          // 0 or 1
        const int gtid  = tid & 255;
        const int gw    = gtid >> 5;         // warp in group, 0-7
        const int mb    = (gw >> 2) * 32;    // 0 / 32 (within 64-row slab)
        const int nb    = (gw & 3) * 32;     // 0/32/64/96

        __half* ActG = Act  + group * (64 * LDW);
        __half* PsG  = Ps_s + group * (64 * LDW);
        __half* PdG  = Pd_s + group * (64 * LDW);
        const uint32_t psb = smem_u32(PsG), pdb = smem_u32(PdG);

        const int ntiles = (E + 63) >> 6;    // 64-row tiles
        for (int tile = blockIdx.x * 2 + group; tile < ntiles; tile += nctas * 2) {
            const int base = tile << 6;
            gbar(group);   // prev tile fully consumed (ActG, stages, s_red)

            // ---- issue P gathers via cp.async (awaited after GEMM1)
            {
                int r = (gtid & 127) >> 1, hf = gtid & 1;
                int e = base + r;
                if (gtid < 128) {
                    int node = (e < E) ? src_idx[e] : 0;
                    const char* srcp = (const char*)g_P + (size_t)node * 512 + hf * 128;
                    uint32_t dstp = psb + (uint32_t)(r * 272 + hf * 128);
                    #pragma unroll
                    for (int j = 0; j < 8; j++) cp16(dstp + j * 16, srcp + j * 16);
                } else {
                    int node = (e < E) ? dst_idx[e] : 0;
                    const char* srcp = (const char*)g_P + (size_t)node * 512 + 256 + hf * 128;
                    uint32_t dstp = pdb + (uint32_t)(r * 272 + hf * 128);
                    #pragma unroll
                    for (int j = 0; j < 8; j++) cp16(dstp + j * 16, srcp + j * 16);
                }
                CP_COMMIT();
            }

            // ---- efeat tile -> fp16 ActG (64 rows)
            #pragma unroll 2
            for (int i = gtid; i < 64 * 32; i += 256) {
                int r = i >> 5, c4 = (i & 31) * 4;
                int e = base + r;
                float4 v = make_float4(0.f, 0.f, 0.f, 0.f);
                if (e < E) v = *(const float4*)(efeat + (size_t)e * 128 + c4);
                *(__half2*)(ActG + r * LDW + c4)     = __floats2half2_rn(v.x, v.y);
                *(__half2*)(ActG + r * LDW + c4 + 2) = __floats2half2_rn(v.z, v.w);
            }
            gbar(group);

            // ---- GEMM1: efeat @ We^T (gathers in flight)
            float acc[2][4][4];
            zero_acc(acc);
            gemm1(ActG, Wsm, acc, mb, nb, lane);

            CP_WAIT0();
            gbar(group);   // group: GEMM1 done + gathers visible

            // ---- epilogue 1: + Ps + Pd (LDS), SiLU, hidden -> ActG
            #pragma unroll
            for (int mi = 0; mi < 2; mi++) {
                int r0 = mb + mi * 16 + g, r1 = r0 + 8;
                #pragma unroll
                for (int ni = 0; ni < 4; ni++) {
                    int col = nb + ni * 8 + t * 2;
                    float2 a = __half22float2(*(__half2*)(PsG + r0 * LDW + col));
                    float2 b = __half22float2(*(__half2*)(PdG + r0 * LDW + col));
                    float2 c = __half22float2(*(__half2*)(PsG + r1 * LDW + col));
                    float2 dd = __half22float2(*(__half2*)(PdG + r1 * LDW + col));
                    float x0 = acc[mi][ni][0] + a.x + b.x;
                    float x1 = acc[mi][ni][1] + a.y + b.y;
                    float x2 = acc[mi][ni][2] + c.x + dd.x;
                    float x3 = acc[mi][ni][3] + c.y + dd.y;
                    x0 = x0 / (1.f + __expf(-x0));
                    x1 = x1 / (1.f + __expf(-x1));
                    x2 = x2 / (1.f + __expf(-x2));
                    x3 = x3 / (1.f + __expf(-x3));
                    *(__half2*)(ActG + r0 * LDW + col) = __floats2half2_rn(x0, x1);
                    *(__half2*)(ActG + r1 * LDW + col) = __floats2half2_rn(x2, x3);
                }
            }
            gbar(group);

            // ---- GEMM2: hidden @ W2^T
            zero_acc(acc);
            gemm1(ActG, Wsm + 128 * LDW, acc, mb, nb, lane);

            // ---- +b2, per-row partial sums -> smem combine (group rows)
            #pragma unroll
            for (int mi = 0; mi < 2; mi++) {
                #pragma unroll
                for (int hr = 0; hr < 2; hr++) {
                    float ss = 0.f, s2 = 0.f;
                    #pragma unroll
                    for (int ni = 0; ni < 4; ni++) {
                        int col = nb + ni * 8 + t * 2;
                        float x0 = acc[mi][ni][hr * 2]     + s_b2[col];
                        float x1 = acc[mi][ni][hr * 2 + 1] + s_b2[col + 1];
                        acc[mi][ni][hr * 2]     = x0;
                        acc[mi][ni][hr * 2 + 1] = x1;
                        ss += x0 + x1;
                        s2 += x0 * x0 + x1 * x1;
                    }
                    ss += __shfl_xor_sync(0xffffffffu, ss, 1);
                    s2 += __shfl_xor_sync(0xffffffffu, s2, 1);
                    ss += __shfl_xor_sync(0xffffffffu, ss, 2);
                    s2 += __shfl_xor_sync(0xffffffffu, s2, 2);
                    if (t == 0) {
                        int r = mb + mi * 16 + g + hr * 8;
                        s_red[(group * 64 + r) * 4 + (nb >> 5)] = make_float2(ss, s2);
                    }
                }
            }
            gbar(group);

            // ---- LayerNorm + store straight from accumulators
            #pragma unroll
            for (int mi = 0; mi < 2; mi++) {
                #pragma unroll
                for (int hr = 0; hr < 2; hr++) {
                    int r = mb + mi * 16 + g + hr * 8;
                    const float2* pr = &s_red[(group * 64 + r) * 4];
                    float2 p0 = pr[0], p1 = pr[1], p2 = pr[2], p3 = pr[3];
                    float ssum = (p0.x + p1.x) + (p2.x + p3.x);
                    float ssq  = (p0.y + p1.y) + (p2.y + p3.y);
                    float mean = ssum * (1.f / 128.f);
                    float var  = ssq * (1.f / 128.f) - mean * mean;
                    float rstd = rsqrtf(var + 1e-5f);
                    int e = base + r;
                    if (e < E) {
                        float* po = out + (size_t)e * 128;
                        #pragma unroll
                        for (int ni = 0; ni < 4; ni++) {
                            int col = nb + ni * 8 + t * 2;
                            float2 v;
                            v.x = (acc[mi][ni][hr * 2]     - mean) * rstd * s_g[col]     + s_bt[col];
                            v.y = (acc[mi][ni][hr * 2 + 1] - mean) * rstd * s_g[col + 1] + s_bt[col + 1];
                            *(float2*)(po + col) = v;
                        }
                    }
                }
            }
        }
    }
}

// ---------------------------------------------------------------------------
extern "C" void kernel_launch(void* const* d_in, const int* in_sizes, int n_in,
                              void* d_out, int out_size)
{
    const float* efeat   = (const float*)d_in[0];
    const float* nfeat   = (const float*)d_in[1];
    const int*   src_idx = (const int*)d_in[2];
    const int*   dst_idx = (const int*)d_in[3];
    const float* w_efeat = (const float*)d_in[4];
    const float* w_src   = (const float*)d_in[5];
    const float* w_dst   = (const float*)d_in[6];
    const float* b1      = (const float*)d_in[7];
    const float* w2      = (const float*)d_in[8];
    const float* b2      = (const float*)d_in[9];
    const float* ln_g    = (const float*)d_in[10];
    const float* ln_b    = (const float*)d_in[11];
    float* out = (float*)d_out;

    const int E = in_sizes[2];
    const int N = in_sizes[1] / 128;

    cudaFuncSetAttribute(fused_kernel, cudaFuncAttributeMaxDynamicSharedMemorySize, SMEM_SZ);

    // 1 CTA/SM persistent grid; fewer CTAs than SMs stays safe for the barrier.
    int nsm = 148;
    if (cudaDeviceGetAttribute(&nsm, cudaDevAttrMultiProcessorCount, 0) != cudaSuccess || nsm <= 0)
        nsm = 148;

    fused_kernel<<<nsm, NT, SMEM_SZ>>>(efeat, nfeat, src_idx, dst_idx,
                                       w_efeat, w_src, w_dst, b1, w2, b2,
                                       ln_g, ln_b, out, E, N);
}

// round 14
// speedup vs baseline: 2.3248x; 1.1925x over previous
#include <cuda_runtime.h>
#include <cuda_fp16.h>
#include <cstdint>

// ===========================================================================
// MeshGraphEdgeMLPSum — single persistent kernel, 3 phases w/ grid barriers:
//   P0: round all 4 weight matrices to fp16 (staged in gmem, padded stride)
//   P1: node projections  P[n] = fp16[ nfeat@Ws^T | nfeat@Wd^T + b1 ]
//   P2: edge pipeline      out = LN( silu(ef@We^T + Ps[src]+Pd[dst]) @ W2^T + b2 )
// fp16 1-term GEMMs, fp32 accumulate, mma.sync.m16n8k16.f16 + ldmatrix.x4.
// R14: phase 2 = two independent 256-thread groups, double-buffered Act,
// software-pipelined: gathers + next-tile efeat prefetched during LN/store;
// 4 named barriers per tile; fast-division SiLU.
// ===========================================================================

#define LDW 136   // padded fp16 row stride (272 B): ldmatrix/LDS conflict-free
#define NT  512   // threads per CTA
#define MATB (128 * LDW * 2)   // 34816 B per fp16 matrix
#define SLAB (64 * LDW)        // halves per 64-row group slab

// ------------------------- globals ----------------------------------------
__device__ __half g_W[4][128 * LDW];   // We, W2, Ws, Wd (fp16, padded)
__device__ __half g_P[50048 * 256];    // [node][0:128]=src proj, [128:256]=dst+b1
__device__ unsigned int g_cnt = 0;     // monotone grid-barrier counter

// ------------------------- smem layout ------------------------------------
#define SM_W     0                       // 2 matrices (per phase) = 69632
#define SM_ACT   69632                   // 2 parity x 2 group x 17408 = 69632
#define SM_PS    139264                  // gather stage src: 2 x 17408
#define SM_PD    174080                  // gather stage dst: 2 x 17408
#define SM_RED   208896                  // float2[128*4] = 4096
#define SM_B2    212992
#define SM_G     213504
#define SM_BT    214016
#define SM_B1    214528
#define SMEM_SZ  215552

// ------------------------- helpers ----------------------------------------
__device__ __forceinline__ uint32_t smem_u32(const void* p) {
    uint32_t a;
    asm("{ .reg .u64 t; cvta.to.shared.u64 t, %1; cvt.u32.u64 %0, t; }" : "=r"(a) : "l"(p));
    return a;
}

__device__ __forceinline__ void ldsm4(uint32_t* r, uint32_t addr) {
    asm volatile("ldmatrix.sync.aligned.m8n8.x4.shared.b16 {%0,%1,%2,%3}, [%4];"
        : "=r"(r[0]), "=r"(r[1]), "=r"(r[2]), "=r"(r[3]) : "r"(addr));
}

__device__ __forceinline__ void mma_f16(float* c, const uint32_t* a, uint32_t b0, uint32_t b1) {
    asm volatile(
        "mma.sync.aligned.m16n8k16.row.col.f32.f16.f16.f32 "
        "{%0,%1,%2,%3}, {%4,%5,%6,%7}, {%8,%9}, {%0,%1,%2,%3};\n"
        : "+f"(c[0]), "+f"(c[1]), "+f"(c[2]), "+f"(c[3])
        : "r"(a[0]), "r"(a[1]), "r"(a[2]), "r"(a[3]), "r"(b0), "r"(b1));
}

__device__ __forceinline__ void cp16(uint32_t dst, const void* src) {
    asm volatile("cp.async.cg.shared.global [%0], [%1], 16;" :: "r"(dst), "l"(src));
}
#define CP_COMMIT() asm volatile("cp.async.commit_group;" ::: "memory")
#define CP_WAIT0()  asm volatile("cp.async.wait_group 0;" ::: "memory")

// group barrier: named barrier (id = group+1), 256 threads
__device__ __forceinline__ void gbar(int group) {
    asm volatile("bar.sync %0, 256;" :: "r"(group + 1) : "memory");
}

// monotone grid barrier: no reset needed across graph replays
__device__ __forceinline__ void grid_barrier(int nctas) {
    __syncthreads();
    if (threadIdx.x == 0) {
        __threadfence();
        unsigned int t = atomicAdd(&g_cnt, 1u) + 1u;
        unsigned int target = ((t + (unsigned)nctas - 1u) / (unsigned)nctas) * (unsigned)nctas;
        unsigned int cur;
        do {
            asm volatile("ld.acquire.gpu.u32 %0, [%1];" : "=r"(cur) : "l"(&g_cnt));
        } while (cur < target);
    }
    __syncthreads();
}

// acc += A @ W^T : fp16 1-term, ldmatrix.x4 fragments. Warp tile 32x32.
__device__ __forceinline__ void gemm1(
    const __half* A, const __half* W,
    float acc[2][4][4], int mbase, int nbase, int lane)
{
    const int rowA = lane & 15;
    const int colA = (lane >> 4) << 3;
    uint32_t aA = smem_u32(A) + (uint32_t)(((mbase + rowA) * LDW + colA) * 2);
    const int rowB = (lane & 7) + ((lane & 16) >> 1);
    const int colB = lane & 8;
    uint32_t aB = smem_u32(W) + (uint32_t)(((nbase + rowB) * LDW + colB) * 2);
    const uint32_t MI = 16 * LDW * 2;

    #pragma unroll
    for (int k0 = 0; k0 < 128; k0 += 16) {
        uint32_t a0[4], a1[4], b[2][4];
        ldsm4(a0, aA + k0 * 2);
        ldsm4(a1, aA + MI + k0 * 2);
        ldsm4(b[0], aB + k0 * 2);
        ldsm4(b[1], aB + MI + k0 * 2);
        #pragma unroll
        for (int ni = 0; ni < 4; ni++) {
            mma_f16(acc[0][ni], a0, b[ni >> 1][(ni & 1) * 2], b[ni >> 1][(ni & 1) * 2 + 1]);
            mma_f16(acc[1][ni], a1, b[ni >> 1][(ni & 1) * 2], b[ni >> 1][(ni & 1) * 2 + 1]);
        }
    }
}

__device__ __forceinline__ void zero_acc(float acc[2][4][4]) {
    #pragma unroll
    for (int mi = 0; mi < 2; mi++)
        #pragma unroll
        for (int ni = 0; ni < 4; ni++)
            #pragma unroll
            for (int j = 0; j < 4; j++)
                acc[mi][ni][j] = 0.f;
}

// ---- phase-2 building blocks ----------------------------------------------
__device__ __forceinline__ void load_efeat_g(const float* __restrict__ efeat,
                                             __half* dst, int base, int gtid, int E)
{
    #pragma unroll 4
    for (int i = gtid; i < 64 * 32; i += 256) {
        int r = i >> 5, c4 = (i & 31) * 4;
        int e = base + r;
        float4 v = make_float4(0.f, 0.f, 0.f, 0.f);
        if (e < E) v = *(const float4*)(efeat + (size_t)e * 128 + c4);
        *(__half2*)(dst + r * LDW + c4)     = __floats2half2_rn(v.x, v.y);
        *(__half2*)(dst + r * LDW + c4 + 2) = __floats2half2_rn(v.z, v.w);
    }
}

__device__ __forceinline__ void issue_gathers(const int* __restrict__ src_idx,
                                              const int* __restrict__ dst_idx,
                                              uint32_t psb, uint32_t pdb,
                                              int base, int gtid, int E)
{
    int r = (gtid & 127) >> 1, hf = gtid & 1;
    int e = base + r;
    if (gtid < 128) {
        int node = (e < E) ? src_idx[e] : 0;
        const char* srcp = (const char*)g_P + (size_t)node * 512 + hf * 128;
        uint32_t dstp = psb + (uint32_t)(r * 272 + hf * 128);
        #pragma unroll
        for (int j = 0; j < 8; j++) cp16(dstp + j * 16, srcp + j * 16);
    } else {
        int node = (e < E) ? dst_idx[e] : 0;
        const char* srcp = (const char*)g_P + (size_t)node * 512 + 256 + hf * 128;
        uint32_t dstp = pdb + (uint32_t)(r * 272 + hf * 128);
        #pragma unroll
        for (int j = 0; j < 8; j++) cp16(dstp + j * 16, srcp + j * 16);
    }
    CP_COMMIT();
}

// ------------------------- the fused persistent kernel --------------------
__global__ __launch_bounds__(NT, 1)
void fused_kernel(const float* __restrict__ efeat, const float* __restrict__ nfeat,
                  const int* __restrict__ src_idx, const int* __restrict__ dst_idx,
                  const float* __restrict__ w_efeat, const float* __restrict__ w_src,
                  const float* __restrict__ w_dst,  const float* __restrict__ b1,
                  const float* __restrict__ w2,     const float* __restrict__ b2,
                  const float* __restrict__ ln_g,   const float* __restrict__ ln_b,
                  float* __restrict__ out, int E, int Nn)
{
    extern __shared__ char sm[];
    __half* Wsm   = (__half*)(sm + SM_W);
    __half* ActA  = (__half*)(sm + SM_ACT);     // [parity*2+group] slabs
    __half* Ps_s  = (__half*)(sm + SM_PS);
    __half* Pd_s  = (__half*)(sm + SM_PD);
    float2* s_red = (float2*)(sm + SM_RED);
    float*  s_b2  = (float*)(sm + SM_B2);
    float*  s_g   = (float*)(sm + SM_G);
    float*  s_bt  = (float*)(sm + SM_BT);
    float*  s_b1  = (float*)(sm + SM_B1);

    const int tid = threadIdx.x;
    const int nctas = gridDim.x;
    const int warp = tid >> 5, lane = tid & 31, g = lane >> 2, t = lane & 3;

    // ---------------- phase 0: weight rounding (fp16, padded) -----------
    {
        const float* srcs[4] = { w_efeat, w2, w_src, w_dst };
        for (int i = blockIdx.x * NT + tid; i < 4 * 16384; i += nctas * NT) {
            int mat = i >> 14, idx = i & 16383;
            int r = idx >> 7, c = idx & 127;
            g_W[mat][r * LDW + c] = __float2half(srcs[mat][r * 128 + c]);
        }
    }
    grid_barrier(nctas);

    // ---------------- phase 1: node projections -> fp16 P ---------------
    {
        __half* Act = ActA;   // contiguous 128-row buffer (parity-0 slabs)
        const int mbase = (warp >> 2) * 32, nbase = (warp & 3) * 32;
        const uint4* s = (const uint4*)g_W[2];   // Ws, Wd
        uint4* d = (uint4*)Wsm;
        for (int i = tid; i < 2 * MATB / 16; i += NT) d[i] = s[i];
        if (tid < 128) s_b1[tid] = b1[tid];
        __syncthreads();

        const int ntile = (Nn + 127) >> 7;
        for (int tile = blockIdx.x; tile < ntile; tile += nctas) {
            const int base = tile << 7;
            __syncthreads();  // prev tile's gemm reads of Act done

            #pragma unroll 2
            for (int i = tid; i < 128 * 32; i += NT) {
                int r = i >> 5, c4 = (i & 31) * 4;
                int node = base + r;
                float4 v = make_float4(0.f, 0.f, 0.f, 0.f);
                if (node < Nn) v = *(const float4*)(nfeat + (size_t)node * 128 + c4);
                *(__half2*)(Act + r * LDW + c4)     = __floats2half2_rn(v.x, v.y);
                *(__half2*)(Act + r * LDW + c4 + 2) = __floats2half2_rn(v.z, v.w);
            }
            __syncthreads();

            #pragma unroll
            for (int half = 0; half < 2; half++) {
                float acc[2][4][4];
                zero_acc(acc);
                gemm1(Act, Wsm + half * 128 * LDW, acc, mbase, nbase, lane);
                #pragma unroll
                for (int mi = 0; mi < 2; mi++) {
                    int r0 = mbase + mi * 16 + g;
                    int n0 = base + r0, n1 = n0 + 8;
                    #pragma unroll
                    for (int ni = 0; ni < 4; ni++) {
                        int col = nbase + ni * 8 + t * 2;
                        float bx = half ? s_b1[col]     : 0.f;
                        float by = half ? s_b1[col + 1] : 0.f;
                        if (n0 < Nn)
                            *(__half2*)(g_P + (size_t)n0 * 256 + half * 128 + col) =
                                __floats2half2_rn(acc[mi][ni][0] + bx, acc[mi][ni][1] + by);
                        if (n1 < Nn)
                            *(__half2*)(g_P + (size_t)n1 * 256 + half * 128 + col) =
                                __floats2half2_rn(acc[mi][ni][2] + bx, acc[mi][ni][3] + by);
                    }
                }
            }
        }
    }
    grid_barrier(nctas);

    // ---------------- phase 2: edge pipeline, 2 groups, pipelined -------
    {
        const uint4* s = (const uint4*)g_W[0];   // We, W2
        uint4* d = (uint4*)Wsm;
        for (int i = tid; i < 2 * MATB / 16; i += NT) d[i] = s[i];
        if (tid < 128) { s_b2[tid] = b2[tid]; s_g[tid] = ln_g[tid]; s_bt[tid] = ln_b[tid]; }
        __syncthreads();   // weights + consts visible to both groups

        const int group = tid >> 8;          // 0 or 1
        const int gtid  = tid & 255;
        const int gw    = gtid >> 5;         // warp in group, 0-7
        const int mb    = (gw >> 2) * 32;    // 0 / 32 (within 64-row slab)
        const int nb    = (gw & 3) * 32;     // 0/32/64/96

        __half* buf[2] = { ActA + (0 * 2 + group) * SLAB, ActA + (1 * 2 + group) * SLAB };
        __half* PsG  = Ps_s + group * SLAB;
        __half* PdG  = Pd_s + group * SLAB;
        const uint32_t psb = smem_u32(PsG), pdb = smem_u32(PdG);

        const int step = nctas * 2;
        const int ntiles = (E + 63) >> 6;    // 64-row tiles
        int tile = blockIdx.x * 2 + group;
        int p = 0;

        // prologue: prefetch first tile
        if (tile < ntiles) {
            issue_gathers(src_idx, dst_idx, psb, pdb, tile << 6, gtid, E);
            load_efeat_g(efeat, buf[p], tile << 6, gtid, E);
        }

        for (; tile < ntiles; tile += step) {
            const int base = tile << 6;
            gbar(group);   // efeat(buf[p]) visible; prev tile fully consumed

            // ---- GEMM1: efeat @ We^T (gathers in flight)
            float acc[2][4][4];
            zero_acc(acc);
            gemm1(buf[p], Wsm, acc, mb, nb, lane);

            CP_WAIT0();
            gbar(group);   // group: GEMM1 done + gathers visible

            // ---- epilogue 1: + Ps + Pd (LDS), fast SiLU, hidden -> buf[p]
            #pragma unroll
            for (int mi = 0; mi < 2; mi++) {
                int r0 = mb + mi * 16 + g, r1 = r0 + 8;
                #pragma unroll
                for (int ni = 0; ni < 4; ni++) {
                    int col = nb + ni * 8 + t * 2;
                    float2 a = __half22float2(*(__half2*)(PsG + r0 * LDW + col));
                    float2 b = __half22float2(*(__half2*)(PdG + r0 * LDW + col));
                    float2 c = __half22float2(*(__half2*)(PsG + r1 * LDW + col));
                    float2 dd = __half22float2(*(__half2*)(PdG + r1 * LDW + col));
                    float x0 = acc[mi][ni][0] + a.x + b.x;
                    float x1 = acc[mi][ni][1] + a.y + b.y;
                    float x2 = acc[mi][ni][2] + c.x + dd.x;
                    float x3 = acc[mi][ni][3] + c.y + dd.y;
                    x0 = __fdividef(x0, 1.f + __expf(-x0));
                    x1 = __fdividef(x1, 1.f + __expf(-x1));
                    x2 = __fdividef(x2, 1.f + __expf(-x2));
                    x3 = __fdividef(x3, 1.f + __expf(-x3));
                    *(__half2*)(buf[p] + r0 * LDW + col) = __floats2half2_rn(x0, x1);
                    *(__half2*)(buf[p] + r1 * LDW + col) = __floats2half2_rn(x2, x3);
                }
            }
            gbar(group);

            // ---- GEMM2: hidden @ W2^T
            zero_acc(acc);
            gemm1(buf[p], Wsm + 128 * LDW, acc, mb, nb, lane);

            // ---- +b2, per-row partial sums -> smem combine (group rows)
            #pragma unroll
            for (int mi = 0; mi < 2; mi++) {
                #pragma unroll
                for (int hr = 0; hr < 2; hr++) {
                    float ss = 0.f, s2 = 0.f;
                    #pragma unroll
                    for (int ni = 0; ni < 4; ni++) {
                        int col = nb + ni * 8 + t * 2;
                        float x0 = acc[mi][ni][hr * 2]     + s_b2[col];
                        float x1 = acc[mi][ni][hr * 2 + 1] + s_b2[col + 1];
                        acc[mi][ni][hr * 2]     = x0;
                        acc[mi][ni][hr * 2 + 1] = x1;
                        ss += x0 + x1;
                        s2 += x0 * x0 + x1 * x1;
                    }
                    ss += __shfl_xor_sync(0xffffffffu, ss, 1);
                    s2 += __shfl_xor_sync(0xffffffffu, s2, 1);
                    ss += __shfl_xor_sync(0xffffffffu, ss, 2);
                    s2 += __shfl_xor_sync(0xffffffffu, s2, 2);
                    if (t == 0) {
                        int r = mb + mi * 16 + g + hr * 8;
                        s_red[(group * 64 + r) * 4 + (nb >> 5)] = make_float2(ss, s2);
                    }
                }
            }
            gbar(group);

            // ---- prefetch NEXT tile (gathers + efeat) while LN runs below
            int ntl = tile + step;
            if (ntl < ntiles) {
                issue_gathers(src_idx, dst_idx, psb, pdb, ntl << 6, gtid, E);
                load_efeat_g(efeat, buf[p ^ 1], ntl << 6, gtid, E);
            }

            // ---- LayerNorm + store straight from accumulators
            #pragma unroll
            for (int mi = 0; mi < 2; mi++) {
                #pragma unroll
                for (int hr = 0; hr < 2; hr++) {
                    int r = mb + mi * 16 + g + hr * 8;
                    const float2* pr = &s_red[(group * 64 + r) * 4];
                    float2 p0 = pr[0], p1 = pr[1], p2 = pr[2], p3 = pr[3];
                    float ssum = (p0.x + p1.x) + (p2.x + p3.x);
                    float ssq  = (p0.y + p1.y) + (p2.y + p3.y);
                    float mean = ssum * (1.f / 128.f);
                    float var  = ssq * (1.f / 128.f) - mean * mean;
                    float rstd = rsqrtf(var + 1e-5f);
                    int e = base + r;
                    if (e < E) {
                        float* po = out + (size_t)e * 128;
                        #pragma unroll
                        for (int ni = 0; ni < 4; ni++) {
                            int col = nb + ni * 8 + t * 2;
                            float2 v;
                            v.x = (acc[mi][ni][hr * 2]     - mean) * rstd * s_g[col]     + s_bt[col];
                            v.y = (acc[mi][ni][hr * 2 + 1] - mean) * rstd * s_g[col + 1] + s_bt[col + 1];
                            *(float2*)(po + col) = v;
                        }
                    }
                }
            }

            p ^= 1;
        }
    }
}

// ---------------------------------------------------------------------------
extern "C" void kernel_launch(void* const* d_in, const int* in_sizes, int n_in,
                              void* d_out, int out_size)
{
    const float* efeat   = (const float*)d_in[0];
    const float* nfeat   = (const float*)d_in[1];
    const int*   src_idx = (const int*)d_in[2];
    const int*   dst_idx = (const int*)d_in[3];
    const float* w_efeat = (const float*)d_in[4];
    const float* w_src   = (const float*)d_in[5];
    const float* w_dst   = (const float*)d_in[6];
    const float* b1      = (const float*)d_in[7];
    const float* w2      = (const float*)d_in[8];
    const float* b2      = (const float*)d_in[9];
    const float* ln_g    = (const float*)d_in[10];
    const float* ln_b    = (const float*)d_in[11];
    float* out = (float*)d_out;

    const int E = in_sizes[2];
    const int N = in_sizes[1] / 128;

    cudaFuncSetAttribute(fused_kernel, cudaFuncAttributeMaxDynamicSharedMemorySize, SMEM_SZ);

    // 1 CTA/SM persistent grid; fewer CTAs than SMs stays safe for the barrier.
    int nsm = 148;
    if (cudaDeviceGetAttribute(&nsm, cudaDevAttrMultiProcessorCount, 0) != cudaSuccess || nsm <= 0)
        nsm = 148;

    fused_kernel<<<nsm, NT, SMEM_SZ>>>(efeat, nfeat, src_idx, dst_idx,
                                       w_efeat, w_src, w_dst, b1, w2, b2,
                                       ln_g, ln_b, out, E, N);
}

// round 15
// speedup vs baseline: 2.4344x; 1.0472x over previous
#include <cuda_runtime.h>
#include <cuda_fp16.h>
#include <cstdint>

// ===========================================================================
// MeshGraphEdgeMLPSum — single persistent kernel, 3 phases w/ grid barriers:
//   P0: round all 4 weight matrices to fp16 (staged in gmem, padded stride)
//   P1: node projections  P[n] = fp16[ nfeat@Ws^T | nfeat@Wd^T + b1 ]
//   P2: edge pipeline      out = LN( silu(ef@We^T + Ps[src]+Pd[dst]) @ W2^T + b2 )
// fp16 1-term GEMMs, fp32 accumulate, mma.sync.m16n8k16.f16 + ldmatrix.x4.
// R15: tanh-based SiLU (1 MUFU/val); epilogue-1 fragments via ldmatrix /
// stmatrix (8+4 matrix ops replace 48 scalar smem ops per warp-tile).
// Two 256-thread groups, double-buffered Act, prefetch during LN.
// ===========================================================================

#define LDW 136   // padded fp16 row stride (272 B): ldmatrix/LDS conflict-free
#define NT  512   // threads per CTA
#define MATB (128 * LDW * 2)   // 34816 B per fp16 matrix
#define SLAB (64 * LDW)        // 64-row group slab (halves)

// ------------------------- globals ----------------------------------------
__device__ __half g_W[4][128 * LDW];   // We, W2, Ws, Wd (fp16, padded)
__device__ __half g_P[50048 * 256];    // [node][0:128]=src proj, [128:256]=dst+b1
__device__ unsigned int g_cnt = 0;     // monotone grid-barrier counter

// ------------------------- smem layout ------------------------------------
#define SM_W     0                       // 2 matrices (per phase) = 69632
#define SM_ACT   69632                   // 2 parity x 2 group x 17408 = 69632
#define SM_PS    139264                  // gather stage src: 2 x 17408
#define SM_PD    174080                  // gather stage dst: 2 x 17408
#define SM_RED   208896                  // float2[128*4] = 4096
#define SM_B2    212992
#define SM_G     213504
#define SM_BT    214016
#define SM_B1    214528
#define SMEM_SZ  215552

// ------------------------- helpers ----------------------------------------
__device__ __forceinline__ uint32_t smem_u32(const void* p) {
    uint32_t a;
    asm("{ .reg .u64 t; cvta.to.shared.u64 t, %1; cvt.u32.u64 %0, t; }" : "=r"(a) : "l"(p));
    return a;
}

__device__ __forceinline__ void ldsm4(uint32_t* r, uint32_t addr) {
    asm volatile("ldmatrix.sync.aligned.m8n8.x4.shared.b16 {%0,%1,%2,%3}, [%4];"
        : "=r"(r[0]), "=r"(r[1]), "=r"(r[2]), "=r"(r[3]) : "r"(addr));
}

__device__ __forceinline__ void stsm4(uint32_t addr, uint32_t v0, uint32_t v1,
                                      uint32_t v2, uint32_t v3) {
    asm volatile("stmatrix.sync.aligned.m8n8.x4.shared.b16 [%0], {%1,%2,%3,%4};"
        :: "r"(addr), "r"(v0), "r"(v1), "r"(v2), "r"(v3) : "memory");
}

__device__ __forceinline__ void mma_f16(float* c, const uint32_t* a, uint32_t b0, uint32_t b1) {
    asm volatile(
        "mma.sync.aligned.m16n8k16.row.col.f32.f16.f16.f32 "
        "{%0,%1,%2,%3}, {%4,%5,%6,%7}, {%8,%9}, {%0,%1,%2,%3};\n"
        : "+f"(c[0]), "+f"(c[1]), "+f"(c[2]), "+f"(c[3])
        : "r"(a[0]), "r"(a[1]), "r"(a[2]), "r"(a[3]), "r"(b0), "r"(b1));
}

__device__ __forceinline__ float silu_f(float x) {
    float h = 0.5f * x, t;
    asm("tanh.approx.f32 %0, %1;" : "=f"(t) : "f"(h));
    return fmaf(h, t, h);   // 0.5x·(1+tanh(x/2)) = x·sigmoid(x)
}

__device__ __forceinline__ void cp16(uint32_t dst, const void* src) {
    asm volatile("cp.async.cg.shared.global [%0], [%1], 16;" :: "r"(dst), "l"(src));
}
#define CP_COMMIT() asm volatile("cp.async.commit_group;" ::: "memory")
#define CP_WAIT0()  asm volatile("cp.async.wait_group 0;" ::: "memory")

// group barrier: named barrier (id = group+1), 256 threads
__device__ __forceinline__ void gbar(int group) {
    asm volatile("bar.sync %0, 256;" :: "r"(group + 1) : "memory");
}

// monotone grid barrier: no reset needed across graph replays
__device__ __forceinline__ void grid_barrier(int nctas) {
    __syncthreads();
    if (threadIdx.x == 0) {
        __threadfence();
        unsigned int t = atomicAdd(&g_cnt, 1u) + 1u;
        unsigned int target = ((t + (unsigned)nctas - 1u) / (unsigned)nctas) * (unsigned)nctas;
        unsigned int cur;
        do {
            asm volatile("ld.acquire.gpu.u32 %0, [%1];" : "=r"(cur) : "l"(&g_cnt));
        } while (cur < target);
    }
    __syncthreads();
}

// acc += A @ W^T : fp16 1-term, ldmatrix.x4 fragments. Warp tile 32x32.
__device__ __forceinline__ void gemm1(
    const __half* A, const __half* W,
    float acc[2][4][4], int mbase, int nbase, int lane)
{
    const int rowA = lane & 15;
    const int colA = (lane >> 4) << 3;
    uint32_t aA = smem_u32(A) + (uint32_t)(((mbase + rowA) * LDW + colA) * 2);
    const int rowB = (lane & 7) + ((lane & 16) >> 1);
    const int colB = lane & 8;
    uint32_t aB = smem_u32(W) + (uint32_t)(((nbase + rowB) * LDW + colB) * 2);
    const uint32_t MI = 16 * LDW * 2;

    #pragma unroll
    for (int k0 = 0; k0 < 128; k0 += 16) {
        uint32_t a0[4], a1[4], b[2][4];
        ldsm4(a0, aA + k0 * 2);
        ldsm4(a1, aA + MI + k0 * 2);
        ldsm4(b[0], aB + k0 * 2);
        ldsm4(b[1], aB + MI + k0 * 2);
        #pragma unroll
        for (int ni = 0; ni < 4; ni++) {
            mma_f16(acc[0][ni], a0, b[ni >> 1][(ni & 1) * 2], b[ni >> 1][(ni & 1) * 2 + 1]);
            mma_f16(acc[1][ni], a1, b[ni >> 1][(ni & 1) * 2], b[ni >> 1][(ni & 1) * 2 + 1]);
        }
    }
}

__device__ __forceinline__ void zero_acc(float acc[2][4][4]) {
    #pragma unroll
    for (int mi = 0; mi < 2; mi++)
        #pragma unroll
        for (int ni = 0; ni < 4; ni++)
            #pragma unroll
            for (int j = 0; j < 4; j++)
                acc[mi][ni][j] = 0.f;
}

// ---- phase-2 building blocks ----------------------------------------------
__device__ __forceinline__ void load_efeat_g(const float* __restrict__ efeat,
                                             __half* dst, int base, int gtid, int E)
{
    #pragma unroll 4
    for (int i = gtid; i < 64 * 32; i += 256) {
        int r = i >> 5, c4 = (i & 31) * 4;
        int e = base + r;
        float4 v = make_float4(0.f, 0.f, 0.f, 0.f);
        if (e < E) v = *(const float4*)(efeat + (size_t)e * 128 + c4);
        __half2 h0 = __floats2half2_rn(v.x, v.y);
        __half2 h1 = __floats2half2_rn(v.z, v.w);
        uint2 pk = make_uint2(*(uint32_t*)&h0, *(uint32_t*)&h1);
        *(uint2*)(dst + r * LDW + c4) = pk;
    }
}

__device__ __forceinline__ void issue_gathers(const int* __restrict__ src_idx,
                                              const int* __restrict__ dst_idx,
                                              uint32_t psb, uint32_t pdb,
                                              int base, int gtid, int E)
{
    int r = (gtid & 127) >> 1, hf = gtid & 1;
    int e = base + r;
    if (gtid < 128) {
        int node = (e < E) ? src_idx[e] : 0;
        const char* srcp = (const char*)g_P + (size_t)node * 512 + hf * 128;
        uint32_t dstp = psb + (uint32_t)(r * 272 + hf * 128);
        #pragma unroll
        for (int j = 0; j < 8; j++) cp16(dstp + j * 16, srcp + j * 16);
    } else {
        int node = (e < E) ? dst_idx[e] : 0;
        const char* srcp = (const char*)g_P + (size_t)node * 512 + 256 + hf * 128;
        uint32_t dstp = pdb + (uint32_t)(r * 272 + hf * 128);
        #pragma unroll
        for (int j = 0; j < 8; j++) cp16(dstp + j * 16, srcp + j * 16);
    }
    CP_COMMIT();
}

// ------------------------- the fused persistent kernel --------------------
__global__ __launch_bounds__(NT, 1)
void fused_kernel(const float* __restrict__ efeat, const float* __restrict__ nfeat,
                  const int* __restrict__ src_idx, const int* __restrict__ dst_idx,
                  const float* __restrict__ w_efeat, const float* __restrict__ w_src,
                  const float* __restrict__ w_dst,  const float* __restrict__ b1,
                  const float* __restrict__ w2,     const float* __restrict__ b2,
                  const float* __restrict__ ln_g,   const float* __restrict__ ln_b,
                  float* __restrict__ out, int E, int Nn)
{
    extern __shared__ char sm[];
    __half* Wsm   = (__half*)(sm + SM_W);
    __half* ActA  = (__half*)(sm + SM_ACT);     // [parity*2+group] slabs
    __half* Ps_s  = (__half*)(sm + SM_PS);
    __half* Pd_s  = (__half*)(sm + SM_PD);
    float2* s_red = (float2*)(sm + SM_RED);
    float*  s_b2  = (float*)(sm + SM_B2);
    float*  s_g   = (float*)(sm + SM_G);
    float*  s_bt  = (float*)(sm + SM_BT);
    float*  s_b1  = (float*)(sm + SM_B1);

    const int tid = threadIdx.x;
    const int nctas = gridDim.x;
    const int warp = tid >> 5, lane = tid & 31, g = lane >> 2, t = lane & 3;

    // ---------------- phase 0: weight rounding (fp16, padded) -----------
    {
        const float* srcs[4] = { w_efeat, w2, w_src, w_dst };
        for (int i = blockIdx.x * NT + tid; i < 4 * 16384; i += nctas * NT) {
            int mat = i >> 14, idx = i & 16383;
            int r = idx >> 7, c = idx & 127;
            g_W[mat][r * LDW + c] = __float2half(srcs[mat][r * 128 + c]);
        }
    }
    grid_barrier(nctas);

    // ---------------- phase 1: node projections -> fp16 P ---------------
    {
        __half* Act = ActA;   // contiguous 128-row buffer (parity-0 slabs)
        const int mbase = (warp >> 2) * 32, nbase = (warp & 3) * 32;
        const uint4* s = (const uint4*)g_W[2];   // Ws, Wd
        uint4* d = (uint4*)Wsm;
        for (int i = tid; i < 2 * MATB / 16; i += NT) d[i] = s[i];
        if (tid < 128) s_b1[tid] = b1[tid];
        __syncthreads();

        const int ntile = (Nn + 127) >> 7;
        for (int tile = blockIdx.x; tile < ntile; tile += nctas) {
            const int base = tile << 7;
            __syncthreads();  // prev tile's gemm reads of Act done

            #pragma unroll 2
            for (int i = tid; i < 128 * 32; i += NT) {
                int r = i >> 5, c4 = (i & 31) * 4;
                int node = base + r;
                float4 v = make_float4(0.f, 0.f, 0.f, 0.f);
                if (node < Nn) v = *(const float4*)(nfeat + (size_t)node * 128 + c4);
                __half2 h0 = __floats2half2_rn(v.x, v.y);
                __half2 h1 = __floats2half2_rn(v.z, v.w);
                uint2 pk = make_uint2(*(uint32_t*)&h0, *(uint32_t*)&h1);
                *(uint2*)(Act + r * LDW + c4) = pk;
            }
            __syncthreads();

            #pragma unroll
            for (int half = 0; half < 2; half++) {
                float acc[2][4][4];
                zero_acc(acc);
                gemm1(Act, Wsm + half * 128 * LDW, acc, mbase, nbase, lane);
                #pragma unroll
                for (int mi = 0; mi < 2; mi++) {
                    int r0 = mbase + mi * 16 + g;
                    int n0 = base + r0, n1 = n0 + 8;
                    #pragma unroll
                    for (int ni = 0; ni < 4; ni++) {
                        int col = nbase + ni * 8 + t * 2;
                        float bx = half ? s_b1[col]     : 0.f;
                        float by = half ? s_b1[col + 1] : 0.f;
                        if (n0 < Nn)
                            *(__half2*)(g_P + (size_t)n0 * 256 + half * 128 + col) =
                                __floats2half2_rn(acc[mi][ni][0] + bx, acc[mi][ni][1] + by);
                        if (n1 < Nn)
                            *(__half2*)(g_P + (size_t)n1 * 256 + half * 128 + col) =
                                __floats2half2_rn(acc[mi][ni][2] + bx, acc[mi][ni][3] + by);
                    }
                }
            }
        }
    }
    grid_barrier(nctas);

    // ---------------- phase 2: edge pipeline, 2 groups, pipelined -------
    {
        const uint4* s = (const uint4*)g_W[0];   // We, W2
        uint4* d = (uint4*)Wsm;
        for (int i = tid; i < 2 * MATB / 16; i += NT) d[i] = s[i];
        if (tid < 128) { s_b2[tid] = b2[tid]; s_g[tid] = ln_g[tid]; s_bt[tid] = ln_b[tid]; }
        __syncthreads();   // weights + consts visible to both groups

        const int group = tid >> 8;          // 0 or 1
        const int gtid  = tid & 255;
        const int gw    = gtid >> 5;         // warp in group, 0-7
        const int mb    = (gw >> 2) * 32;    // 0 / 32 (within 64-row slab)
        const int nb    = (gw & 3) * 32;     // 0/32/64/96

        __half* buf[2] = { ActA + (0 * 2 + group) * SLAB, ActA + (1 * 2 + group) * SLAB };
        __half* PsG  = Ps_s + group * SLAB;
        __half* PdG  = Pd_s + group * SLAB;
        const uint32_t psb = smem_u32(PsG), pdb = smem_u32(PdG);

        // fragment lane addressing for ldsm/stsm in epilogue 1:
        // lane k -> row (k&7), col 8*(k>>3) within the warp's 16x32 sub-tile
        const int fr = lane & 7, fc = (lane >> 3) << 3;
        const uint32_t foff = (uint32_t)((mb + fr) * 272 + (nb + fc) * 2);
        const uint32_t fps = psb + foff, fpd = pdb + foff;
        const uint32_t hb[2] = { smem_u32(buf[0]) + foff, smem_u32(buf[1]) + foff };

        const int step = nctas * 2;
        const int ntiles = (E + 63) >> 6;    // 64-row tiles
        int tile = blockIdx.x * 2 + group;
        int p = 0;

        // prologue: prefetch first tile
        if (tile < ntiles) {
            issue_gathers(src_idx, dst_idx, psb, pdb, tile << 6, gtid, E);
            load_efeat_g(efeat, buf[p], tile << 6, gtid, E);
        }

        for (; tile < ntiles; tile += step) {
            const int base = tile << 6;
            gbar(group);   // efeat(buf[p]) visible; prev tile fully consumed

            // ---- GEMM1: efeat @ We^T (gathers in flight)
            float acc[2][4][4];
            zero_acc(acc);
            gemm1(buf[p], Wsm, acc, mb, nb, lane);

            CP_WAIT0();
            gbar(group);   // group: GEMM1 done + gathers visible

            // ---- epilogue 1: + Ps + Pd (ldsm), tanh-SiLU, hidden -> buf[p] (stsm)
            #pragma unroll
            for (int mi = 0; mi < 2; mi++) {
                const uint32_t o = (uint32_t)(mi * 16 * 272);
                uint32_t ps0[4], ps1[4], pd0[4], pd1[4];
                ldsm4(ps0, fps + o);
                ldsm4(ps1, fps + o + 8 * 272);
                ldsm4(pd0, fpd + o);
                ldsm4(pd1, fpd + o + 8 * 272);
                uint32_t v0[4], v1[4];
                #pragma unroll
                for (int ni = 0; ni < 4; ni++) {
                    __half2 q0h = __hadd2(*(__half2*)&ps0[ni], *(__half2*)&pd0[ni]);
                    __half2 q1h = __hadd2(*(__half2*)&ps1[ni], *(__half2*)&pd1[ni]);
                    float2 q0 = __half22float2(q0h);
                    float2 q1 = __half22float2(q1h);
                    float x0 = silu_f(acc[mi][ni][0] + q0.x);
                    float x1 = silu_f(acc[mi][ni][1] + q0.y);
                    float x2 = silu_f(acc[mi][ni][2] + q1.x);
                    float x3 = silu_f(acc[mi][ni][3] + q1.y);
                    __half2 h0 = __floats2half2_rn(x0, x1);
                    __half2 h1 = __floats2half2_rn(x2, x3);
                    v0[ni] = *(uint32_t*)&h0;
                    v1[ni] = *(uint32_t*)&h1;
                }
                stsm4(hb[p] + o,           v0[0], v0[1], v0[2], v0[3]);
                stsm4(hb[p] + o + 8 * 272, v1[0], v1[1], v1[2], v1[3]);
            }
            gbar(group);

            // ---- GEMM2: hidden @ W2^T
            zero_acc(acc);
            gemm1(buf[p], Wsm + 128 * LDW, acc, mb, nb, lane);

            // ---- +b2, per-row partial sums -> smem combine (group rows)
            #pragma unroll
            for (int mi = 0; mi < 2; mi++) {
                #pragma unroll
                for (int hr = 0; hr < 2; hr++) {
                    float ss = 0.f, s2 = 0.f;
                    #pragma unroll
                    for (int ni = 0; ni < 4; ni++) {
                        int col = nb + ni * 8 + t * 2;
                        float x0 = acc[mi][ni][hr * 2]     + s_b2[col];
                        float x1 = acc[mi][ni][hr * 2 + 1] + s_b2[col + 1];
                        acc[mi][ni][hr * 2]     = x0;
                        acc[mi][ni][hr * 2 + 1] = x1;
                        ss += x0 + x1;
                        s2 += x0 * x0 + x1 * x1;
                    }
                    ss += __shfl_xor_sync(0xffffffffu, ss, 1);
                    s2 += __shfl_xor_sync(0xffffffffu, s2, 1);
                    ss += __shfl_xor_sync(0xffffffffu, ss, 2);
                    s2 += __shfl_xor_sync(0xffffffffu, s2, 2);
                    if (t == 0) {
                        int r = mb + mi * 16 + g + hr * 8;
                        s_red[(group * 64 + r) * 4 + (nb >> 5)] = make_float2(ss, s2);
                    }
                }
            }
            gbar(group);

            // ---- prefetch NEXT tile (gathers + efeat) while LN runs below
            int ntl = tile + step;
            if (ntl < ntiles) {
                issue_gathers(src_idx, dst_idx, psb, pdb, ntl << 6, gtid, E);
                load_efeat_g(efeat, buf[p ^ 1], ntl << 6, gtid, E);
            }

            // ---- LayerNorm + store straight from accumulators
            #pragma unroll
            for (int mi = 0; mi < 2; mi++) {
                #pragma unroll
                for (int hr = 0; hr < 2; hr++) {
                    int r = mb + mi * 16 + g + hr * 8;
                    const float2* pr = &s_red[(group * 64 + r) * 4];
                    float2 p0 = pr[0], p1 = pr[1], p2 = pr[2], p3 = pr[3];
                    float ssum = (p0.x + p1.x) + (p2.x + p3.x);
                    float ssq  = (p0.y + p1.y) + (p2.y + p3.y);
                    float mean = ssum * (1.f / 128.f);
                    float var  = ssq * (1.f / 128.f) - mean * mean;
                    float rstd = rsqrtf(var + 1e-5f);
                    int e = base + r;
                    if (e < E) {
                        float* po = out + (size_t)e * 128;
                        #pragma unroll
                        for (int ni = 0; ni < 4; ni++) {
                            int col = nb + ni * 8 + t * 2;
                            float2 v;
                            v.x = (acc[mi][ni][hr * 2]     - mean) * rstd * s_g[col]     + s_bt[col];
                            v.y = (acc[mi][ni][hr * 2 + 1] - mean) * rstd * s_g[col + 1] + s_bt[col + 1];
                            *(float2*)(po + col) = v;
                        }
                    }
                }
            }

            p ^= 1;
        }
    }
}

// ---------------------------------------------------------------------------
extern "C" void kernel_launch(void* const* d_in, const int* in_sizes, int n_in,
                              void* d_out, int out_size)
{
    const float* efeat   = (const float*)d_in[0];
    const float* nfeat   = (const float*)d_in[1];
    const int*   src_idx = (const int*)d_in[2];
    const int*   dst_idx = (const int*)d_in[3];
    const float* w_efeat = (const float*)d_in[4];
    const float* w_src   = (const float*)d_in[5];
    const float* w_dst   = (const float*)d_in[6];
    const float* b1      = (const float*)d_in[7];
    const float* w2      = (const float*)d_in[8];
    const float* b2      = (const float*)d_in[9];
    const float* ln_g    = (const float*)d_in[10];
    const float* ln_b    = (const float*)d_in[11];
    float* out = (float*)d_out;

    const int E = in_sizes[2];
    const int N = in_sizes[1] / 128;

    cudaFuncSetAttribute(fused_kernel, cudaFuncAttributeMaxDynamicSharedMemorySize, SMEM_SZ);

    // 1 CTA/SM persistent grid; fewer CTAs than SMs stays safe for the barrier.
    int nsm = 148;
    if (cudaDeviceGetAttribute(&nsm, cudaDevAttrMultiProcessorCount, 0) != cudaSuccess || nsm <= 0)
        nsm = 148;

    fused_kernel<<<nsm, NT, SMEM_SZ>>>(efeat, nfeat, src_idx, dst_idx,
                                       w_efeat, w_src, w_dst, b1, w2, b2,
                                       ln_g, ln_b, out, E, N);
}

// round 16
// speedup vs baseline: 2.6713x; 1.0973x over previous
#include <cuda_runtime.h>
#include <cuda_fp16.h>
#include <cstdint>

// ===========================================================================
// MeshGraphEdgeMLPSum — single persistent kernel, 3 phases w/ grid barriers:
//   P0: round all 4 weight matrices to fp16 (staged in gmem, padded stride)
//   P1: node projections  P[n] = fp16[ nfeat@Ws^T | nfeat@Wd^T + b1 ]
//   P2: edge pipeline      out = LN( silu(ef@We^T + Ps[src]+Pd[dst]) @ W2^T + b2 )
// fp16 1-term GEMMs, fp32 accumulate, mma.sync.m16n8k16.f16 + ldmatrix.x4.
// R16: phase 2 = FOUR independent 128-thread pipelines (one named barrier
// each), 32-row tiles, all dependencies pipeline-local -> 4-way phase overlap.
// tanh SiLU, ldsm/stsm epilogue-1, cp.async gathers, double-buffered Act.
// ===========================================================================

#define LDW 136   // padded fp16 row stride (272 B): ldmatrix/LDS conflict-free
#define NT  512   // threads per CTA
#define MATB (128 * LDW * 2)   // 34816 B per fp16 matrix
#define HSLAB (32 * LDW)       // 32-row pipeline slab (halves)

// ------------------------- globals ----------------------------------------
__device__ __half g_W[4][128 * LDW];   // We, W2, Ws, Wd (fp16, padded)
__device__ __half g_P[50048 * 256];    // [node][0:128]=src proj, [128:256]=dst+b1
__device__ unsigned int g_cnt = 0;     // monotone grid-barrier counter

// ------------------------- smem layout ------------------------------------
#define SM_W     0                       // 2 matrices (per phase) = 69632
#define SM_ACT   69632                   // 2 parity x 4 pipe x 8704 = 69632
#define SM_PS    139264                  // gather stage src: 4 x 8704
#define SM_PD    174080                  // gather stage dst: 4 x 8704
#define SM_RED   208896                  // float2[128*4] = 4096
#define SM_B2    212992
#define SM_G     213504
#define SM_BT    214016
#define SM_B1    214528
#define SMEM_SZ  215552

// ------------------------- helpers ----------------------------------------
__device__ __forceinline__ uint32_t smem_u32(const void* p) {
    uint32_t a;
    asm("{ .reg .u64 t; cvta.to.shared.u64 t, %1; cvt.u32.u64 %0, t; }" : "=r"(a) : "l"(p));
    return a;
}

__device__ __forceinline__ void ldsm4(uint32_t* r, uint32_t addr) {
    asm volatile("ldmatrix.sync.aligned.m8n8.x4.shared.b16 {%0,%1,%2,%3}, [%4];"
        : "=r"(r[0]), "=r"(r[1]), "=r"(r[2]), "=r"(r[3]) : "r"(addr));
}

__device__ __forceinline__ void stsm4(uint32_t addr, uint32_t v0, uint32_t v1,
                                      uint32_t v2, uint32_t v3) {
    asm volatile("stmatrix.sync.aligned.m8n8.x4.shared.b16 [%0], {%1,%2,%3,%4};"
        :: "r"(addr), "r"(v0), "r"(v1), "r"(v2), "r"(v3) : "memory");
}

__device__ __forceinline__ void mma_f16(float* c, const uint32_t* a, uint32_t b0, uint32_t b1) {
    asm volatile(
        "mma.sync.aligned.m16n8k16.row.col.f32.f16.f16.f32 "
        "{%0,%1,%2,%3}, {%4,%5,%6,%7}, {%8,%9}, {%0,%1,%2,%3};\n"
        : "+f"(c[0]), "+f"(c[1]), "+f"(c[2]), "+f"(c[3])
        : "r"(a[0]), "r"(a[1]), "r"(a[2]), "r"(a[3]), "r"(b0), "r"(b1));
}

__device__ __forceinline__ float silu_f(float x) {
    float h = 0.5f * x, t;
    asm("tanh.approx.f32 %0, %1;" : "=f"(t) : "f"(h));
    return fmaf(h, t, h);   // 0.5x·(1+tanh(x/2)) = x·sigmoid(x)
}

__device__ __forceinline__ void cp16(uint32_t dst, const void* src) {
    asm volatile("cp.async.cg.shared.global [%0], [%1], 16;" :: "r"(dst), "l"(src));
}
#define CP_COMMIT() asm volatile("cp.async.commit_group;" ::: "memory")
#define CP_WAIT0()  asm volatile("cp.async.wait_group 0;" ::: "memory")

// pipeline barrier: named barrier (id = pipe+1), 128 threads
__device__ __forceinline__ void pbar(int pipe) {
    asm volatile("bar.sync %0, 128;" :: "r"(pipe + 1) : "memory");
}

// monotone grid barrier: no reset needed across graph replays
__device__ __forceinline__ void grid_barrier(int nctas) {
    __syncthreads();
    if (threadIdx.x == 0) {
        __threadfence();
        unsigned int t = atomicAdd(&g_cnt, 1u) + 1u;
        unsigned int target = ((t + (unsigned)nctas - 1u) / (unsigned)nctas) * (unsigned)nctas;
        unsigned int cur;
        do {
            asm volatile("ld.acquire.gpu.u32 %0, [%1];" : "=r"(cur) : "l"(&g_cnt));
        } while (cur < target);
    }
    __syncthreads();
}

// acc += A @ W^T : fp16 1-term, ldmatrix.x4 fragments. Warp tile 32x32.
__device__ __forceinline__ void gemm1(
    const __half* A, const __half* W,
    float acc[2][4][4], int mbase, int nbase, int lane)
{
    const int rowA = lane & 15;
    const int colA = (lane >> 4) << 3;
    uint32_t aA = smem_u32(A) + (uint32_t)(((mbase + rowA) * LDW + colA) * 2);
    const int rowB = (lane & 7) + ((lane & 16) >> 1);
    const int colB = lane & 8;
    uint32_t aB = smem_u32(W) + (uint32_t)(((nbase + rowB) * LDW + colB) * 2);
    const uint32_t MI = 16 * LDW * 2;

    #pragma unroll
    for (int k0 = 0; k0 < 128; k0 += 16) {
        uint32_t a0[4], a1[4], b[2][4];
        ldsm4(a0, aA + k0 * 2);
        ldsm4(a1, aA + MI + k0 * 2);
        ldsm4(b[0], aB + k0 * 2);
        ldsm4(b[1], aB + MI + k0 * 2);
        #pragma unroll
        for (int ni = 0; ni < 4; ni++) {
            mma_f16(acc[0][ni], a0, b[ni >> 1][(ni & 1) * 2], b[ni >> 1][(ni & 1) * 2 + 1]);
            mma_f16(acc[1][ni], a1, b[ni >> 1][(ni & 1) * 2], b[ni >> 1][(ni & 1) * 2 + 1]);
        }
    }
}

__device__ __forceinline__ void zero_acc(float acc[2][4][4]) {
    #pragma unroll
    for (int mi = 0; mi < 2; mi++)
        #pragma unroll
        for (int ni = 0; ni < 4; ni++)
            #pragma unroll
            for (int j = 0; j < 4; j++)
                acc[mi][ni][j] = 0.f;
}

// ---- phase-2 building blocks (32-row pipeline tiles) ----------------------
__device__ __forceinline__ void load_efeat_p(const float* __restrict__ efeat,
                                             __half* dst, int base, int ptid, int E)
{
    #pragma unroll 4
    for (int i = ptid; i < 32 * 32; i += 128) {
        int r = i >> 5, c4 = (i & 31) * 4;
        int e = base + r;
        float4 v = make_float4(0.f, 0.f, 0.f, 0.f);
        if (e < E) v = *(const float4*)(efeat + (size_t)e * 128 + c4);
        __half2 h0 = __floats2half2_rn(v.x, v.y);
        __half2 h1 = __floats2half2_rn(v.z, v.w);
        uint2 pk = make_uint2(*(uint32_t*)&h0, *(uint32_t*)&h1);
        *(uint2*)(dst + r * LDW + c4) = pk;
    }
}

__device__ __forceinline__ void issue_gathers_p(const int* __restrict__ src_idx,
                                                const int* __restrict__ dst_idx,
                                                uint32_t psb, uint32_t pdb,
                                                int base, int ptid, int E)
{
    // 32 rows x {src,dst} x 2 half-rows = 128 tasks, one per thread
    int r = (ptid & 63) >> 1, hf = ptid & 1;
    int e = base + r;
    if (ptid < 64) {
        int node = (e < E) ? src_idx[e] : 0;
        const char* srcp = (const char*)g_P + (size_t)node * 512 + hf * 128;
        uint32_t dstp = psb + (uint32_t)(r * 272 + hf * 128);
        #pragma unroll
        for (int j = 0; j < 8; j++) cp16(dstp + j * 16, srcp + j * 16);
    } else {
        int node = (e < E) ? dst_idx[e] : 0;
        const char* srcp = (const char*)g_P + (size_t)node * 512 + 256 + hf * 128;
        uint32_t dstp = pdb + (uint32_t)(r * 272 + hf * 128);
        #pragma unroll
        for (int j = 0; j < 8; j++) cp16(dstp + j * 16, srcp + j * 16);
    }
    CP_COMMIT();
}

// ------------------------- the fused persistent kernel --------------------
__global__ __launch_bounds__(NT, 1)
void fused_kernel(const float* __restrict__ efeat, const float* __restrict__ nfeat,
                  const int* __restrict__ src_idx, const int* __restrict__ dst_idx,
                  const float* __restrict__ w_efeat, const float* __restrict__ w_src,
                  const float* __restrict__ w_dst,  const float* __restrict__ b1,
                  const float* __restrict__ w2,     const float* __restrict__ b2,
                  const float* __restrict__ ln_g,   const float* __restrict__ ln_b,
                  float* __restrict__ out, int E, int Nn)
{
    extern __shared__ char sm[];
    __half* Wsm   = (__half*)(sm + SM_W);
    __half* ActA  = (__half*)(sm + SM_ACT);     // [parity*4+pipe] 32-row slabs
    __half* Ps_s  = (__half*)(sm + SM_PS);
    __half* Pd_s  = (__half*)(sm + SM_PD);
    float2* s_red = (float2*)(sm + SM_RED);     // [(pipe*32+r)*4 + nquad]
    float*  s_b2  = (float*)(sm + SM_B2);
    float*  s_g   = (float*)(sm + SM_G);
    float*  s_bt  = (float*)(sm + SM_BT);
    float*  s_b1  = (float*)(sm + SM_B1);

    const int tid = threadIdx.x;
    const int nctas = gridDim.x;
    const int warp = tid >> 5, lane = tid & 31, g = lane >> 2, t = lane & 3;

    // ---------------- phase 0: weight rounding (fp16, padded) -----------
    {
        const float* srcs[4] = { w_efeat, w2, w_src, w_dst };
        for (int i = blockIdx.x * NT + tid; i < 4 * 16384; i += nctas * NT) {
            int mat = i >> 14, idx = i & 16383;
            int r = idx >> 7, c = idx & 127;
            g_W[mat][r * LDW + c] = __float2half(srcs[mat][r * 128 + c]);
        }
    }
    grid_barrier(nctas);

    // ---------------- phase 1: node projections -> fp16 P ---------------
    {
        __half* Act = ActA;   // parity-0 slabs are contiguous 128 rows
        const int mbase = (warp >> 2) * 32, nbase = (warp & 3) * 32;
        const uint4* s = (const uint4*)g_W[2];   // Ws, Wd
        uint4* d = (uint4*)Wsm;
        for (int i = tid; i < 2 * MATB / 16; i += NT) d[i] = s[i];
        if (tid < 128) s_b1[tid] = b1[tid];
        __syncthreads();

        const int ntile = (Nn + 127) >> 7;
        for (int tile = blockIdx.x; tile < ntile; tile += nctas) {
            const int base = tile << 7;
            __syncthreads();  // prev tile's gemm reads of Act done

            #pragma unroll 2
            for (int i = tid; i < 128 * 32; i += NT) {
                int r = i >> 5, c4 = (i & 31) * 4;
                int node = base + r;
                float4 v = make_float4(0.f, 0.f, 0.f, 0.f);
                if (node < Nn) v = *(const float4*)(nfeat + (size_t)node * 128 + c4);
                __half2 h0 = __floats2half2_rn(v.x, v.y);
                __half2 h1 = __floats2half2_rn(v.z, v.w);
                uint2 pk = make_uint2(*(uint32_t*)&h0, *(uint32_t*)&h1);
                *(uint2*)(Act + r * LDW + c4) = pk;
            }
            __syncthreads();

            #pragma unroll
            for (int half = 0; half < 2; half++) {
                float acc[2][4][4];
                zero_acc(acc);
                gemm1(Act, Wsm + half * 128 * LDW, acc, mbase, nbase, lane);
                #pragma unroll
                for (int mi = 0; mi < 2; mi++) {
                    int r0 = mbase + mi * 16 + g;
                    int n0 = base + r0, n1 = n0 + 8;
                    #pragma unroll
                    for (int ni = 0; ni < 4; ni++) {
                        int col = nbase + ni * 8 + t * 2;
                        float bx = half ? s_b1[col]     : 0.f;
                        float by = half ? s_b1[col + 1] : 0.f;
                        if (n0 < Nn)
                            *(__half2*)(g_P + (size_t)n0 * 256 + half * 128 + col) =
                                __floats2half2_rn(acc[mi][ni][0] + bx, acc[mi][ni][1] + by);
                        if (n1 < Nn)
                            *(__half2*)(g_P + (size_t)n1 * 256 + half * 128 + col) =
                                __floats2half2_rn(acc[mi][ni][2] + bx, acc[mi][ni][3] + by);
                    }
                }
            }
        }
    }
    grid_barrier(nctas);

    // ---------------- phase 2: FOUR independent 128-thread pipelines ----
    {
        const uint4* s = (const uint4*)g_W[0];   // We, W2
        uint4* d = (uint4*)Wsm;
        for (int i = tid; i < 2 * MATB / 16; i += NT) d[i] = s[i];
        if (tid < 128) { s_b2[tid] = b2[tid]; s_g[tid] = ln_g[tid]; s_bt[tid] = ln_b[tid]; }
        __syncthreads();   // weights + consts visible to all pipelines

        const int pipe = tid >> 7;           // 0..3
        const int ptid = tid & 127;
        const int pw   = ptid >> 5;          // warp in pipeline, 0..3
        const int nb   = pw * 32;            // warp's 32-col N slice

        __half* buf[2] = { ActA + (0 * 4 + pipe) * HSLAB, ActA + (1 * 4 + pipe) * HSLAB };
        __half* PsP  = Ps_s + pipe * HSLAB;
        __half* PdP  = Pd_s + pipe * HSLAB;
        const uint32_t psb = smem_u32(PsP), pdb = smem_u32(PdP);

        // fragment lane addressing for ldsm/stsm in epilogue 1 (mb = 0):
        const int fr = lane & 7, fc = (lane >> 3) << 3;
        const uint32_t foff = (uint32_t)(fr * 272 + (nb + fc) * 2);
        const uint32_t fps = psb + foff, fpd = pdb + foff;
        const uint32_t hb[2] = { smem_u32(buf[0]) + foff, smem_u32(buf[1]) + foff };

        const int step = nctas * 4;
        const int ntiles = (E + 31) >> 5;    // 32-row tiles
        int tile = blockIdx.x * 4 + pipe;
        int p = 0;

        // prologue: prefetch first tile
        if (tile < ntiles) {
            issue_gathers_p(src_idx, dst_idx, psb, pdb, tile << 5, ptid, E);
            load_efeat_p(efeat, buf[p], tile << 5, ptid, E);
        }

        for (; tile < ntiles; tile += step) {
            const int base = tile << 5;
            pbar(pipe);   // efeat(buf[p]) visible; prev tile fully consumed

            // ---- GEMM1: efeat @ We^T (gathers in flight)
            float acc[2][4][4];
            zero_acc(acc);
            gemm1(buf[p], Wsm, acc, 0, nb, lane);

            CP_WAIT0();
            pbar(pipe);   // pipeline: GEMM1 done + gathers visible

            // ---- epilogue 1: + Ps + Pd (ldsm), tanh-SiLU, hidden -> buf[p] (stsm)
            #pragma unroll
            for (int mi = 0; mi < 2; mi++) {
                const uint32_t o = (uint32_t)(mi * 16 * 272);
                uint32_t ps0[4], ps1[4], pd0[4], pd1[4];
                ldsm4(ps0, fps + o);
                ldsm4(ps1, fps + o + 8 * 272);
                ldsm4(pd0, fpd + o);
                ldsm4(pd1, fpd + o + 8 * 272);
                uint32_t v0[4], v1[4];
                #pragma unroll
                for (int ni = 0; ni < 4; ni++) {
                    __half2 q0h = __hadd2(*(__half2*)&ps0[ni], *(__half2*)&pd0[ni]);
                    __half2 q1h = __hadd2(*(__half2*)&ps1[ni], *(__half2*)&pd1[ni]);
                    float2 q0 = __half22float2(q0h);
                    float2 q1 = __half22float2(q1h);
                    float x0 = silu_f(acc[mi][ni][0] + q0.x);
                    float x1 = silu_f(acc[mi][ni][1] + q0.y);
                    float x2 = silu_f(acc[mi][ni][2] + q1.x);
                    float x3 = silu_f(acc[mi][ni][3] + q1.y);
                    __half2 h0 = __floats2half2_rn(x0, x1);
                    __half2 h1 = __floats2half2_rn(x2, x3);
                    v0[ni] = *(uint32_t*)&h0;
                    v1[ni] = *(uint32_t*)&h1;
                }
                stsm4(hb[p] + o,           v0[0], v0[1], v0[2], v0[3]);
                stsm4(hb[p] + o + 8 * 272, v1[0], v1[1], v1[2], v1[3]);
            }
            pbar(pipe);

            // ---- GEMM2: hidden @ W2^T
            zero_acc(acc);
            gemm1(buf[p], Wsm + 128 * LDW, acc, 0, nb, lane);

            // ---- +b2, per-row partial sums -> smem combine (pipeline rows)
            #pragma unroll
            for (int mi = 0; mi < 2; mi++) {
                #pragma unroll
                for (int hr = 0; hr < 2; hr++) {
                    float ss = 0.f, s2 = 0.f;
                    #pragma unroll
                    for (int ni = 0; ni < 4; ni++) {
                        int col = nb + ni * 8 + t * 2;
                        float x0 = acc[mi][ni][hr * 2]     + s_b2[col];
                        float x1 = acc[mi][ni][hr * 2 + 1] + s_b2[col + 1];
                        acc[mi][ni][hr * 2]     = x0;
                        acc[mi][ni][hr * 2 + 1] = x1;
                        ss += x0 + x1;
                        s2 += x0 * x0 + x1 * x1;
                    }
                    ss += __shfl_xor_sync(0xffffffffu, ss, 1);
                    s2 += __shfl_xor_sync(0xffffffffu, s2, 1);
                    ss += __shfl_xor_sync(0xffffffffu, ss, 2);
                    s2 += __shfl_xor_sync(0xffffffffu, s2, 2);
                    if (t == 0) {
                        int r = mi * 16 + g + hr * 8;
                        s_red[(pipe * 32 + r) * 4 + pw] = make_float2(ss, s2);
                    }
                }
            }
            pbar(pipe);

            // ---- prefetch NEXT tile (gathers + efeat) while LN runs below
            int ntl = tile + step;
            if (ntl < ntiles) {
                issue_gathers_p(src_idx, dst_idx, psb, pdb, ntl << 5, ptid, E);
                load_efeat_p(efeat, buf[p ^ 1], ntl << 5, ptid, E);
            }

            // ---- LayerNorm + store straight from accumulators
            #pragma unroll
            for (int mi = 0; mi < 2; mi++) {
                #pragma unroll
                for (int hr = 0; hr < 2; hr++) {
                    int r = mi * 16 + g + hr * 8;
                    const float2* pr = &s_red[(pipe * 32 + r) * 4];
                    float2 p0 = pr[0], p1 = pr[1], p2 = pr[2], p3 = pr[3];
                    float ssum = (p0.x + p1.x) + (p2.x + p3.x);
                    float ssq  = (p0.y + p1.y) + (p2.y + p3.y);
                    float mean = ssum * (1.f / 128.f);
                    float var  = ssq * (1.f / 128.f) - mean * mean;
                    float rstd = rsqrtf(var + 1e-5f);
                    int e = base + r;
                    if (e < E) {
                        float* po = out + (size_t)e * 128;
                        #pragma unroll
                        for (int ni = 0; ni < 4; ni++) {
                            int col = nb + ni * 8 + t * 2;
                            float2 v;
                            v.x = (acc[mi][ni][hr * 2]     - mean) * rstd * s_g[col]     + s_bt[col];
                            v.y = (acc[mi][ni][hr * 2 + 1] - mean) * rstd * s_g[col + 1] + s_bt[col + 1];
                            *(float2*)(po + col) = v;
                        }
                    }
                }
            }

            p ^= 1;
        }
    }
}

// ---------------------------------------------------------------------------
extern "C" void kernel_launch(void* const* d_in, const int* in_sizes, int n_in,
                              void* d_out, int out_size)
{
    const float* efeat   = (const float*)d_in[0];
    const float* nfeat   = (const float*)d_in[1];
    const int*   src_idx = (const int*)d_in[2];
    const int*   dst_idx = (const int*)d_in[3];
    const float* w_efeat = (const float*)d_in[4];
    const float* w_src   = (const float*)d_in[5];
    const float* w_dst   = (const float*)d_in[6];
    const float* b1      = (const float*)d_in[7];
    const float* w2      = (const float*)d_in[8];
    const float* b2      = (const float*)d_in[9];
    const float* ln_g    = (const float*)d_in[10];
    const float* ln_b    = (const float*)d_in[11];
    float* out = (float*)d_out;

    const int E = in_sizes[2];
    const int N = in_sizes[1] / 128;

    cudaFuncSetAttribute(fused_kernel, cudaFuncAttributeMaxDynamicSharedMemorySize, SMEM_SZ);

    // 1 CTA/SM persistent grid; fewer CTAs than SMs stays safe for the barrier.
    int nsm = 148;
    if (cudaDeviceGetAttribute(&nsm, cudaDevAttrMultiProcessorCount, 0) != cudaSuccess || nsm <= 0)
        nsm = 148;

    fused_kernel<<<nsm, NT, SMEM_SZ>>>(efeat, nfeat, src_idx, dst_idx,
                                       w_efeat, w_src, w_dst, b1, w2, b2,
                                       ln_g, ln_b, out, E, N);
}